// round 10
// baseline (speedup 1.0000x reference)
#include <cuda_runtime.h>
#include <cuda_bf16.h>
#include <cuda_fp16.h>
#include <math.h>
#include <cstdint>

#define NR   8192
#define DIM  64
#define HID  512
#define LAT  128

// Scratch (device globals — allocation-free per harness rules)
__device__ __half g_H1[2 * NR * HID];    // 16 MB
__device__ __half g_H2[2 * NR * HID];    // 16 MB
__device__ __half g_Zf[2 * NR * LAT];    //  4 MB
__device__ __half g_WT1[HID * DIM];
__device__ __half g_WT2[HID * HID];
__device__ __half g_WT3[LAT * HID];

// ===========================================================================
// helpers
// ===========================================================================
__device__ __forceinline__ uint32_t smem_u32(const void* p) {
    uint32_t a;
    asm("{ .reg .u64 t; cvta.to.shared.u64 t, %1; cvt.u32.u64 %0, t; }"
        : "=r"(a) : "l"(p));
    return a;
}
__device__ __forceinline__ void ldmx4(uint32_t* r, uint32_t addr) {
    asm volatile("ldmatrix.sync.aligned.m8n8.x4.shared.b16 {%0,%1,%2,%3}, [%4];"
                 : "=r"(r[0]), "=r"(r[1]), "=r"(r[2]), "=r"(r[3]) : "r"(addr));
}
__device__ __forceinline__ void mma16816h(float* d, const uint32_t* a,
                                          uint32_t b0, uint32_t b1) {
    asm volatile(
        "mma.sync.aligned.m16n8k16.row.col.f32.f16.f16.f32 "
        "{%0,%1,%2,%3}, {%4,%5,%6,%7}, {%8,%9}, {%0,%1,%2,%3};"
        : "+f"(d[0]), "+f"(d[1]), "+f"(d[2]), "+f"(d[3])
        : "r"(a[0]), "r"(a[1]), "r"(a[2]), "r"(a[3]), "r"(b0), "r"(b1));
}
__device__ __forceinline__ void cpa16(uint32_t dst, const void* src) {
    asm volatile("cp.async.cg.shared.global [%0], [%1], 16;"
                 :: "r"(dst), "l"(src));
}
#define CP_COMMIT() asm volatile("cp.async.commit_group;")
#define CP_WAIT0()  asm volatile("cp.async.wait_group 0;" ::: "memory")
#define CP_WAIT1()  asm volatile("cp.async.wait_group 1;" ::: "memory")

__device__ __forceinline__ uint32_t packh2(float a, float b) {
    uint32_t r;
    asm("cvt.rn.f16x2.f32 %0, %1, %2;" : "=r"(r) : "f"(b), "f"(a));
    return r;
}

// ===========================================================================
// prep kernels (2 launches so layer2 lands at captured launch #4)
// ===========================================================================
__global__ void prep_w2(const float* __restrict__ W,
                        __half* __restrict__ WT) {
    int idx = blockIdx.x * blockDim.x + threadIdx.x;
    if (idx >= HID * HID) return;
    int n = idx / HID, k = idx - n * HID;
    WT[idx] = __float2half(W[(size_t)k * HID + n]);
}
__global__ void prep_w13(const float* __restrict__ W1s, const float* __restrict__ W3s,
                         __half* __restrict__ WT1d, __half* __restrict__ WT3d) {
    int idx = blockIdx.x * blockDim.x + threadIdx.x;
    if (idx < HID * DIM) {
        int n = idx / DIM, k = idx - n * DIM;        // WT1[n*DIM+k] = W1[k*HID+n]
        WT1d[idx] = __float2half(W1s[(size_t)k * HID + n]);
    } else if (idx < HID * DIM + LAT * HID) {
        int j = idx - HID * DIM;
        int n = j / HID, k = j - n * HID;            // WT3[n*HID+k] = W3[k*LAT+n]
        WT3d[j] = __float2half(W3s[(size_t)k * LAT + n]);
    }
}

// ===========================================================================
// Encoder mma GEMM (layers 1,2), single-pass fp16, double-buffered.
// CTA 128x128, BK=64, 8 warps (4x2), 2 CTAs/SM. bias+ReLU -> fp16.
// ===========================================================================
#define ESTR      144
#define ET        (128 * ESTR)
#define ENC_SMEM  (4 * ET)

template<int K, bool A_FP32>
__global__ __launch_bounds__(256, 2) void gemm_enc(
    const void* __restrict__ Ax, const void* __restrict__ Ay,
    const __half* __restrict__ B,
    const float* __restrict__ bias,
    __half* __restrict__ Cf, int Ntot)
{
    constexpr int CH = K / 64;
    extern __shared__ char smem[];
    const uint32_t sbase = smem_u32(smem);
    const int tid = threadIdx.x;
    const int bmg = blockIdx.y << 7, bn = blockIdx.x << 7;
    const int wid = tid >> 5, lane = tid & 31;
    const int wm = (wid & 3) << 5, wn = (wid >> 2) << 6;
    const int lrow = lane & 15, khalf = lane >> 4;

    const float* Af32 = nullptr;
    const __half* Af16 = nullptr;
    int bm;
    if (A_FP32) {
        Af32 = (bmg < NR) ? (const float*)Ax : (const float*)Ay;
        bm = (bmg < NR) ? bmg : bmg - NR;
    } else {
        Af16 = (const __half*)Ax;
        bm = bmg;
    }

    float acc[2][8][4];
#pragma unroll
    for (int mt = 0; mt < 2; mt++)
#pragma unroll
        for (int nt = 0; nt < 8; nt++)
#pragma unroll
            for (int e = 0; e < 4; e++) acc[mt][nt][e] = 0.f;

    const int lr  = tid >> 1;
    const int ksg = (tid & 1) << 5;

    auto load_chunk = [&](int c, int buf) {
        const uint32_t abase = sbase + (uint32_t)(buf * 2) * ET;
        const uint32_t bbase = abase + ET;
        const uint32_t ob = (uint32_t)lr * ESTR + (uint32_t)ksg * 2;
        if (A_FP32) {
            const float* ap = Af32 + (size_t)(bm + lr) * K + c * 64 + ksg;
#pragma unroll
            for (int q = 0; q < 4; q++) {
                float4 f0 = *(const float4*)(ap + q * 8);
                float4 f1 = *(const float4*)(ap + q * 8 + 4);
                uint4 v;
                v.x = packh2(f0.x, f0.y); v.y = packh2(f0.z, f0.w);
                v.z = packh2(f1.x, f1.y); v.w = packh2(f1.z, f1.w);
                *(uint4*)(smem + (abase - sbase) + ob + q * 16) = v;
            }
        } else {
            const char* ap = (const char*)(Af16 + (size_t)(bm + lr) * K + c * 64 + ksg);
#pragma unroll
            for (int q = 0; q < 4; q++)
                cpa16(abase + ob + q * 16, ap + q * 16);
        }
        const char* bp = (const char*)(B + (size_t)(bn + lr) * K + c * 64 + ksg);
#pragma unroll
        for (int q = 0; q < 4; q++)
            cpa16(bbase + ob + q * 16, bp + q * 16);
    };

    load_chunk(0, 0);
    CP_COMMIT();

    for (int c = 0; c < CH; c++) {
        if (c + 1 < CH) {
            load_chunk(c + 1, (c + 1) & 1);
            CP_COMMIT();
            CP_WAIT1();
        } else {
            CP_WAIT0();
        }
        __syncthreads();

        const uint32_t abase = sbase + (uint32_t)((c & 1) * 2) * ET;
        const uint32_t bbase = abase + ET;
#pragma unroll
        for (int ks = 0; ks < 4; ks++) {
            const uint32_t koff = (uint32_t)ks * 32 + (uint32_t)khalf * 16;
            uint32_t a[2][4];
#pragma unroll
            for (int mt = 0; mt < 2; mt++) {
                const uint32_t ra = (uint32_t)(wm + mt * 16 + lrow) * ESTR + koff;
                ldmx4(a[mt], abase + ra);
            }
#pragma unroll
            for (int np = 0; np < 4; np++) {
                const uint32_t rb = (uint32_t)(wn + np * 16 + lrow) * ESTR + koff;
                uint32_t t[4];
                ldmx4(t, bbase + rb);
#pragma unroll
                for (int mt = 0; mt < 2; mt++) {
                    mma16816h(acc[mt][2*np+0], a[mt], t[0], t[2]);
                    mma16816h(acc[mt][2*np+1], a[mt], t[1], t[3]);
                }
            }
        }
        __syncthreads();
    }

    const int r_in = lane >> 2;
    const int c_in = (lane & 3) << 1;

    float bias2[8][2];
#pragma unroll
    for (int nt = 0; nt < 8; nt++) {
        bias2[nt][0] = bias[bn + wn + nt * 8 + c_in];
        bias2[nt][1] = bias[bn + wn + nt * 8 + c_in + 1];
    }

#pragma unroll
    for (int mt = 0; mt < 2; mt++) {
        const int r0 = bmg + wm + mt * 16 + r_in;
#pragma unroll
        for (int nt = 0; nt < 8; nt++) {
            float o0 = fmaxf(acc[mt][nt][0] + bias2[nt][0], 0.f);
            float o1 = fmaxf(acc[mt][nt][1] + bias2[nt][1], 0.f);
            float o2 = fmaxf(acc[mt][nt][2] + bias2[nt][0], 0.f);
            float o3 = fmaxf(acc[mt][nt][3] + bias2[nt][1], 0.f);
            const int col = bn + wn + nt * 8 + c_in;
            *(uint32_t*)(Cf + (size_t)r0 * Ntot + col)       = packh2(o0, o1);
            *(uint32_t*)(Cf + (size_t)(r0 + 8) * Ntot + col) = packh2(o2, o3);
        }
    }
}

// ===========================================================================
// Layer 3 + L2 norm: CTA 64x128, K=512 (BK=64, double-buffered), 8 warps
// (2 M x 4 N), grid (1, 512) -> full-chip. Output fp16 Z.
// ===========================================================================
#define N3_A      (64 * ESTR)            // 9216
#define N3_B      (128 * ESTR)           // 18432
#define N3_AB     (N3_A + N3_B)          // 27648
#define N3_SMEM   (2 * N3_AB)            // 55296

__global__ __launch_bounds__(256, 2) void gemm_norm64(
    const __half* __restrict__ A, const __half* __restrict__ B,
    const float* __restrict__ bias, __half* __restrict__ Zf)
{
    constexpr int K = HID, CH = K / 64, Ntot = LAT;
    extern __shared__ char smem[];
    const uint32_t sbase = smem_u32(smem);
    const int tid = threadIdx.x;
    const int bmg = blockIdx.y << 6;
    const int wid = tid >> 5, lane = tid & 31;
    const int wm = (wid & 1) << 5, wn = (wid >> 1) << 5;
    const int lrow = lane & 15, khalf = lane >> 4;

    float acc[2][4][4];
#pragma unroll
    for (int mt = 0; mt < 2; mt++)
#pragma unroll
        for (int nt = 0; nt < 4; nt++)
#pragma unroll
            for (int e = 0; e < 4; e++) acc[mt][nt][e] = 0.f;

    const int lra = tid >> 2, ka = (tid & 3) << 4;   // A: 64 rows x 32B
    const int lrb = tid >> 1, kb = (tid & 1) << 5;   // B: 128 rows x 64B

    auto load_chunk = [&](int c, int buf) {
        const uint32_t abase = sbase + (uint32_t)buf * N3_AB;
        const uint32_t bbase = abase + N3_A;
        const uint32_t oa = (uint32_t)lra * ESTR + (uint32_t)ka * 2;
        const char* ap = (const char*)(A + (size_t)(bmg + lra) * K + c * 64 + ka);
        cpa16(abase + oa,      ap);
        cpa16(abase + oa + 16, ap + 16);
        const uint32_t obp = (uint32_t)lrb * ESTR + (uint32_t)kb * 2;
        const char* bp = (const char*)(B + (size_t)lrb * K + c * 64 + kb);
#pragma unroll
        for (int q = 0; q < 4; q++)
            cpa16(bbase + obp + q * 16, bp + q * 16);
    };

    load_chunk(0, 0);
    CP_COMMIT();

    for (int c = 0; c < CH; c++) {
        if (c + 1 < CH) {
            load_chunk(c + 1, (c + 1) & 1);
            CP_COMMIT();
            CP_WAIT1();
        } else {
            CP_WAIT0();
        }
        __syncthreads();

        const uint32_t abase = sbase + (uint32_t)(c & 1) * N3_AB;
        const uint32_t bbase = abase + N3_A;
#pragma unroll
        for (int ks = 0; ks < 4; ks++) {
            const uint32_t koff = (uint32_t)ks * 32 + (uint32_t)khalf * 16;
            uint32_t a[2][4];
#pragma unroll
            for (int mt = 0; mt < 2; mt++)
                ldmx4(a[mt], abase + (uint32_t)(wm + mt * 16 + lrow) * ESTR + koff);
#pragma unroll
            for (int np = 0; np < 2; np++) {
                uint32_t t[4];
                ldmx4(t, bbase + (uint32_t)(wn + np * 16 + lrow) * ESTR + koff);
#pragma unroll
                for (int mt = 0; mt < 2; mt++) {
                    mma16816h(acc[mt][2*np+0], a[mt], t[0], t[2]);
                    mma16816h(acc[mt][2*np+1], a[mt], t[1], t[3]);
                }
            }
        }
        __syncthreads();
    }

    const int r_in = lane >> 2;
    const int c_in = (lane & 3) << 1;

    float bias2[4][2];
#pragma unroll
    for (int nt = 0; nt < 4; nt++) {
        bias2[nt][0] = bias[wn + nt * 8 + c_in];
        bias2[nt][1] = bias[wn + nt * 8 + c_in + 1];
    }

    float ss[2][2] = {{0.f, 0.f}, {0.f, 0.f}};
#pragma unroll
    for (int mt = 0; mt < 2; mt++)
#pragma unroll
        for (int nt = 0; nt < 4; nt++) {
            acc[mt][nt][0] += bias2[nt][0];
            acc[mt][nt][1] += bias2[nt][1];
            acc[mt][nt][2] += bias2[nt][0];
            acc[mt][nt][3] += bias2[nt][1];
            ss[mt][0] = fmaf(acc[mt][nt][0], acc[mt][nt][0],
                        fmaf(acc[mt][nt][1], acc[mt][nt][1], ss[mt][0]));
            ss[mt][1] = fmaf(acc[mt][nt][2], acc[mt][nt][2],
                        fmaf(acc[mt][nt][3], acc[mt][nt][3], ss[mt][1]));
        }
#pragma unroll
    for (int m = 1; m <= 2; m <<= 1) {
#pragma unroll
        for (int mt = 0; mt < 2; mt++) {
            ss[mt][0] += __shfl_xor_sync(0xFFFFFFFFu, ss[mt][0], m);
            ss[mt][1] += __shfl_xor_sync(0xFFFFFFFFu, ss[mt][1], m);
        }
    }
    float* red  = (float*)smem;          // [64][4]
    float* invp = red + 256;             // [64]
    const int wcol = wid >> 1;
    if ((lane & 3) == 0) {
#pragma unroll
        for (int mt = 0; mt < 2; mt++) {
            red[(wm + mt * 16 + r_in) * 4 + wcol]     = ss[mt][0];
            red[(wm + mt * 16 + r_in + 8) * 4 + wcol] = ss[mt][1];
        }
    }
    __syncthreads();
    if (tid < 64) {
        float s = red[tid * 4] + red[tid * 4 + 1] + red[tid * 4 + 2] + red[tid * 4 + 3];
        invp[tid] = 1.f / fmaxf(sqrtf(s), 1e-12f);
    }
    __syncthreads();
#pragma unroll
    for (int mt = 0; mt < 2; mt++) {
        const int rl = wm + mt * 16 + r_in;
        const float inv0 = invp[rl], inv1 = invp[rl + 8];
        const int r0 = bmg + rl;
#pragma unroll
        for (int nt = 0; nt < 4; nt++) {
            const int col = wn + nt * 8 + c_in;
            *(uint32_t*)(Zf + (size_t)r0 * Ntot + col) =
                packh2(acc[mt][nt][0] * inv0, acc[mt][nt][1] * inv0);
            *(uint32_t*)(Zf + (size_t)(r0 + 8) * Ntot + col) =
                packh2(acc[mt][nt][2] * inv1, acc[mt][nt][3] * inv1);
        }
    }
}

// ===========================================================================
// Final NT GEMM: C = Zx @ Zy^T, K=128, fp16. CTA = 128x256 strip (2 tiles),
// A loaded once, B double-buffered; 3 barriers/CTA; 8 warps 4x2; 2 CTAs/SM.
// ===========================================================================
#define FSTR      272
#define F_A       0
#define F_B0      (128 * FSTR)
#define F_B1      (F_B0 + 128 * FSTR)
#define NTF_SMEM  (3 * 128 * FSTR)       // 104448 B

__global__ __launch_bounds__(256, 2) void gemm_nt_f16(
    const __half* __restrict__ ZA, const __half* __restrict__ ZB,
    float* __restrict__ C)
{
    extern __shared__ char smem[];
    const uint32_t sbase = smem_u32(smem);
    const int tid = threadIdx.x;
    const int bm = blockIdx.y << 7;
    const int bn = blockIdx.x << 8;          // 256-col strip (2 tiles)

    const int row  = tid >> 1;
    const int half = tid & 1;
    const uint32_t dof = (uint32_t)row * FSTR + (uint32_t)half * 128;

    // group 0: A + B0 ; group 1: B1
    {
        const char* sa = (const char*)(ZA + (size_t)(bm + row) * LAT + half * 64);
        const char* sb = (const char*)(ZB + (size_t)(bn + row) * LAT + half * 64);
#pragma unroll
        for (int c = 0; c < 8; c++) {
            cpa16(sbase + F_A  + dof + c * 16, sa + c * 16);
            cpa16(sbase + F_B0 + dof + c * 16, sb + c * 16);
        }
    }
    CP_COMMIT();
    {
        const char* sb = (const char*)(ZB + (size_t)(bn + 128 + row) * LAT + half * 64);
#pragma unroll
        for (int c = 0; c < 8; c++)
            cpa16(sbase + F_B1 + dof + c * 16, sb + c * 16);
    }
    CP_COMMIT();

    const int wid  = tid >> 5;
    const int lane = tid & 31;
    const int wm = (wid & 3) << 5;
    const int wn = (wid >> 2) << 6;
    const int lrow  = lane & 15;
    const int khalf = lane >> 4;
    const int r_in = lane >> 2;
    const int c_in = (lane & 3) << 1;

    CP_WAIT1();
    __syncthreads();

    float acc[2][8][4];

#pragma unroll
    for (int t = 0; t < 2; t++) {
        const uint32_t bbase = sbase + (t ? F_B1 : F_B0);
#pragma unroll
        for (int mt = 0; mt < 2; mt++)
#pragma unroll
            for (int nt = 0; nt < 8; nt++)
#pragma unroll
                for (int e = 0; e < 4; e++) acc[mt][nt][e] = 0.f;

#pragma unroll
        for (int ks = 0; ks < 8; ks++) {
            const uint32_t koff = (uint32_t)ks * 32 + (uint32_t)khalf * 16;
            uint32_t a[2][4];
#pragma unroll
            for (int mt = 0; mt < 2; mt++) {
                const uint32_t ra = (uint32_t)(wm + mt * 16 + lrow) * FSTR + koff;
                ldmx4(a[mt], sbase + F_A + ra);
            }
#pragma unroll
            for (int np = 0; np < 4; np++) {
                const uint32_t rb = (uint32_t)(wn + np * 16 + lrow) * FSTR + koff;
                uint32_t b[4];
                ldmx4(b, bbase + rb);
#pragma unroll
                for (int mt = 0; mt < 2; mt++) {
                    mma16816h(acc[mt][2*np+0], a[mt], b[0], b[2]);
                    mma16816h(acc[mt][2*np+1], a[mt], b[1], b[3]);
                }
            }
        }

        if (t == 0) {
            CP_WAIT0();          // B1 landed (already issued long ago)
            __syncthreads();     // make B1 visible before tile-1 ldmatrix
        }

        const int r0 = bm + wm + r_in;
        const int c0 = bn + t * 128 + wn + c_in;
#pragma unroll
        for (int mt = 0; mt < 2; mt++) {
#pragma unroll
            for (int nt = 0; nt < 8; nt++) {
                float* p0 = C + (size_t)(r0 + mt * 16)     * NR + c0 + nt * 8;
                float* p1 = C + (size_t)(r0 + mt * 16 + 8) * NR + c0 + nt * 8;
                *(float2*)p0 = make_float2(acc[mt][nt][0], acc[mt][nt][1]);
                *(float2*)p1 = make_float2(acc[mt][nt][2], acc[mt][nt][3]);
            }
        }
    }
}

// ===========================================================================
extern "C" void kernel_launch(void* const* d_in, const int* in_sizes, int n_in,
                              void* d_out, int out_size)
{
    const float* x  = (const float*)d_in[0];
    const float* y  = (const float*)d_in[1];
    const float* W1 = (const float*)d_in[2];
    const float* b1 = (const float*)d_in[3];
    const float* W2 = (const float*)d_in[4];
    const float* b2 = (const float*)d_in[5];
    const float* W3 = (const float*)d_in[6];
    const float* b3 = (const float*)d_in[7];
    float* out = (float*)d_out;

    __half *H1, *H2, *Zf, *WT1, *WT2, *WT3;
    cudaGetSymbolAddress((void**)&H1,  g_H1);
    cudaGetSymbolAddress((void**)&H2,  g_H2);
    cudaGetSymbolAddress((void**)&Zf,  g_Zf);
    cudaGetSymbolAddress((void**)&WT1, g_WT1);
    cudaGetSymbolAddress((void**)&WT2, g_WT2);
    cudaGetSymbolAddress((void**)&WT3, g_WT3);

    cudaFuncSetAttribute(gemm_nt_f16, cudaFuncAttributeMaxDynamicSharedMemorySize, NTF_SMEM);
    cudaFuncSetAttribute(gemm_norm64, cudaFuncAttributeMaxDynamicSharedMemorySize, N3_SMEM);
    cudaFuncSetAttribute(gemm_enc<64,  true>,  cudaFuncAttributeMaxDynamicSharedMemorySize, ENC_SMEM);
    cudaFuncSetAttribute(gemm_enc<512, false>, cudaFuncAttributeMaxDynamicSharedMemorySize, ENC_SMEM);

    // launch 1, 2: weight prep
    prep_w13<<<(HID * DIM + LAT * HID + 255) / 256, 256>>>(W1, W3, WT1, WT3);
    prep_w2 <<<(HID * HID + 255) / 256, 256>>>(W2, WT2);

    // launch 3: layer 1 (fp32 x/y fused)
    dim3 g1(HID / 128, 2 * NR / 128);
    gemm_enc<64, true><<<g1, 256, ENC_SMEM>>>(x, y, WT1, b1, H1, HID);

    // launch 4 (profiled): layer 2
    dim3 g2(HID / 128, 2 * NR / 128);
    gemm_enc<512, false><<<g2, 256, ENC_SMEM>>>(H1, nullptr, WT2, b2, H2, HID);

    // launch 5: layer 3 + L2 norm (64-row tiles, full-chip)
    dim3 g3(1, 2 * NR / 64);
    gemm_norm64<<<g3, 256, N3_SMEM>>>(H2, WT3, b3, Zf);

    // launch 6: similarity (2-tile strips)
    dim3 g4(NR / 256, NR / 128);
    gemm_nt_f16<<<g4, 256, NTF_SMEM>>>(Zf, Zf + (size_t)NR * LAT, out);
}

// round 11
// speedup vs baseline: 1.0557x; 1.0557x over previous
#include <cuda_runtime.h>
#include <cuda_bf16.h>
#include <cuda_fp16.h>
#include <math.h>
#include <cstdint>

#define NR   8192
#define DIM  64
#define HID  512
#define LAT  128

// Scratch (device globals — allocation-free per harness rules)
__device__ __half g_H1[2 * NR * HID];    // 16 MB
__device__ __half g_H2[2 * NR * HID];    // 16 MB
__device__ __half g_Zf[2 * NR * LAT];    //  4 MB
__device__ __half g_WT1[HID * DIM];
__device__ __half g_WT2[HID * HID];
__device__ __half g_WT3[LAT * HID];

// ===========================================================================
// helpers
// ===========================================================================
__device__ __forceinline__ uint32_t smem_u32(const void* p) {
    uint32_t a;
    asm("{ .reg .u64 t; cvta.to.shared.u64 t, %1; cvt.u32.u64 %0, t; }"
        : "=r"(a) : "l"(p));
    return a;
}
__device__ __forceinline__ void ldmx4(uint32_t* r, uint32_t addr) {
    asm volatile("ldmatrix.sync.aligned.m8n8.x4.shared.b16 {%0,%1,%2,%3}, [%4];"
                 : "=r"(r[0]), "=r"(r[1]), "=r"(r[2]), "=r"(r[3]) : "r"(addr));
}
__device__ __forceinline__ void mma16816h(float* d, const uint32_t* a,
                                          uint32_t b0, uint32_t b1) {
    asm volatile(
        "mma.sync.aligned.m16n8k16.row.col.f32.f16.f16.f32 "
        "{%0,%1,%2,%3}, {%4,%5,%6,%7}, {%8,%9}, {%0,%1,%2,%3};"
        : "+f"(d[0]), "+f"(d[1]), "+f"(d[2]), "+f"(d[3])
        : "r"(a[0]), "r"(a[1]), "r"(a[2]), "r"(a[3]), "r"(b0), "r"(b1));
}
__device__ __forceinline__ void cpa16(uint32_t dst, const void* src) {
    asm volatile("cp.async.cg.shared.global [%0], [%1], 16;"
                 :: "r"(dst), "l"(src));
}
#define CP_COMMIT() asm volatile("cp.async.commit_group;")
#define CP_WAIT0()  asm volatile("cp.async.wait_group 0;" ::: "memory")

__device__ __forceinline__ uint32_t packh2(float a, float b) {
    uint32_t r;
    asm("cvt.rn.f16x2.f32 %0, %1, %2;" : "=r"(r) : "f"(b), "f"(a));
    return r;
}

// ===========================================================================
// prep kernels (2 launches so layer2 lands at captured launch #4)
// ===========================================================================
__global__ void prep_w2(const float* __restrict__ W,
                        __half* __restrict__ WT) {
    int idx = blockIdx.x * blockDim.x + threadIdx.x;
    if (idx >= HID * HID) return;
    int n = idx / HID, k = idx - n * HID;
    WT[idx] = __float2half(W[(size_t)k * HID + n]);
}
__global__ void prep_w13(const float* __restrict__ W1s, const float* __restrict__ W3s,
                         __half* __restrict__ WT1d, __half* __restrict__ WT3d) {
    int idx = blockIdx.x * blockDim.x + threadIdx.x;
    if (idx < HID * DIM) {
        int n = idx / DIM, k = idx - n * DIM;
        WT1d[idx] = __float2half(W1s[(size_t)k * HID + n]);
    } else if (idx < HID * DIM + LAT * HID) {
        int j = idx - HID * DIM;
        int n = j / HID, k = j - n * HID;
        WT3d[j] = __float2half(W3s[(size_t)k * LAT + n]);
    }
}

// ===========================================================================
// Encoder mma GEMM (layers 1,2), fp16, double-buffered, 1 barrier/chunk,
// register-level fragment pipelining. CTA 128x128, BK=64, 8 warps (4x2).
// ===========================================================================
#define ESTR      144
#define ET        (128 * ESTR)
#define ENC_SMEM  (4 * ET)

template<int K, bool A_FP32>
__global__ __launch_bounds__(256, 2) void gemm_enc(
    const void* __restrict__ Ax, const void* __restrict__ Ay,
    const __half* __restrict__ B,
    const float* __restrict__ bias,
    __half* __restrict__ Cf, int Ntot)
{
    constexpr int CH = K / 64;
    extern __shared__ char smem[];
    const uint32_t sbase = smem_u32(smem);
    const int tid = threadIdx.x;
    const int bmg = blockIdx.y << 7, bn = blockIdx.x << 7;
    const int wid = tid >> 5, lane = tid & 31;
    const int wm = (wid & 3) << 5, wn = (wid >> 2) << 6;
    const int lrow = lane & 15, khalf = lane >> 4;

    const float* Af32 = nullptr;
    const __half* Af16 = nullptr;
    int bm;
    if (A_FP32) {
        Af32 = (bmg < NR) ? (const float*)Ax : (const float*)Ay;
        bm = (bmg < NR) ? bmg : bmg - NR;
    } else {
        Af16 = (const __half*)Ax;
        bm = bmg;
    }

    float acc[2][8][4];
#pragma unroll
    for (int mt = 0; mt < 2; mt++)
#pragma unroll
        for (int nt = 0; nt < 8; nt++)
#pragma unroll
            for (int e = 0; e < 4; e++) acc[mt][nt][e] = 0.f;

    const int lr  = tid >> 1;
    const int ksg = (tid & 1) << 5;

    auto load_chunk = [&](int c, int buf) {
        const uint32_t abase = sbase + (uint32_t)(buf * 2) * ET;
        const uint32_t bbase = abase + ET;
        const uint32_t ob = (uint32_t)lr * ESTR + (uint32_t)ksg * 2;
        if (A_FP32) {
            const float* ap = Af32 + (size_t)(bm + lr) * K + c * 64 + ksg;
#pragma unroll
            for (int q = 0; q < 4; q++) {
                float4 f0 = *(const float4*)(ap + q * 8);
                float4 f1 = *(const float4*)(ap + q * 8 + 4);
                uint4 v;
                v.x = packh2(f0.x, f0.y); v.y = packh2(f0.z, f0.w);
                v.z = packh2(f1.x, f1.y); v.w = packh2(f1.z, f1.w);
                *(uint4*)(smem + (abase - sbase) + ob + q * 16) = v;
            }
        } else {
            const char* ap = (const char*)(Af16 + (size_t)(bm + lr) * K + c * 64 + ksg);
#pragma unroll
            for (int q = 0; q < 4; q++)
                cpa16(abase + ob + q * 16, ap + q * 16);
        }
        const char* bp = (const char*)(B + (size_t)(bn + lr) * K + c * 64 + ksg);
#pragma unroll
        for (int q = 0; q < 4; q++)
            cpa16(bbase + ob + q * 16, bp + q * 16);
    };

    load_chunk(0, 0);
    CP_COMMIT();

    for (int c = 0; c < CH; c++) {
        CP_WAIT0();
        __syncthreads();    // chunk c visible; all warps done reading buf (c+1)&1
        if (c + 1 < CH) {
            load_chunk(c + 1, (c + 1) & 1);
            CP_COMMIT();
        }

        const uint32_t abase = sbase + (uint32_t)((c & 1) * 2) * ET;
        const uint32_t bbase = abase + ET;

        // ---- fragment-pipelined mma over 4 k-steps ----
        uint32_t af[2][2][4], bf[2][4];
#pragma unroll
        for (int mt = 0; mt < 2; mt++)
            ldmx4(af[0][mt], abase + (uint32_t)(wm + mt * 16 + lrow) * ESTR
                             + (uint32_t)khalf * 16);
        ldmx4(bf[0], bbase + (uint32_t)(wn + lrow) * ESTR + (uint32_t)khalf * 16);

#pragma unroll
        for (int ks = 0; ks < 4; ks++) {
            if (ks + 1 < 4) {
#pragma unroll
                for (int mt = 0; mt < 2; mt++)
                    ldmx4(af[(ks + 1) & 1][mt],
                          abase + (uint32_t)(wm + mt * 16 + lrow) * ESTR
                                + (uint32_t)((ks + 1) * 32 + khalf * 16));
            }
#pragma unroll
            for (int np = 0; np < 4; np++) {
                const int idx = ks * 4 + np;
                if (idx + 1 < 16) {
                    const int nks = (idx + 1) >> 2, nnp = (idx + 1) & 3;
                    ldmx4(bf[(idx + 1) & 1],
                          bbase + (uint32_t)(wn + nnp * 16 + lrow) * ESTR
                                + (uint32_t)(nks * 32 + khalf * 16));
                }
                const uint32_t* bc = bf[idx & 1];
#pragma unroll
                for (int mt = 0; mt < 2; mt++) {
                    mma16816h(acc[mt][2*np+0], af[ks & 1][mt], bc[0], bc[2]);
                    mma16816h(acc[mt][2*np+1], af[ks & 1][mt], bc[1], bc[3]);
                }
            }
        }
    }

    const int r_in = lane >> 2;
    const int c_in = (lane & 3) << 1;

    float bias2[8][2];
#pragma unroll
    for (int nt = 0; nt < 8; nt++) {
        bias2[nt][0] = bias[bn + wn + nt * 8 + c_in];
        bias2[nt][1] = bias[bn + wn + nt * 8 + c_in + 1];
    }

#pragma unroll
    for (int mt = 0; mt < 2; mt++) {
        const int r0 = bmg + wm + mt * 16 + r_in;
#pragma unroll
        for (int nt = 0; nt < 8; nt++) {
            float o0 = fmaxf(acc[mt][nt][0] + bias2[nt][0], 0.f);
            float o1 = fmaxf(acc[mt][nt][1] + bias2[nt][1], 0.f);
            float o2 = fmaxf(acc[mt][nt][2] + bias2[nt][0], 0.f);
            float o3 = fmaxf(acc[mt][nt][3] + bias2[nt][1], 0.f);
            const int col = bn + wn + nt * 8 + c_in;
            *(uint32_t*)(Cf + (size_t)r0 * Ntot + col)       = packh2(o0, o1);
            *(uint32_t*)(Cf + (size_t)(r0 + 8) * Ntot + col) = packh2(o2, o3);
        }
    }
}

// ===========================================================================
// Layer 3 + L2 norm: CTA 64x128, K=512 (BK=64, double-buffered), 8 warps
// (2 M x 4 N), grid (1, 512) -> full-chip. Output fp16 Z. (round-10 config)
// ===========================================================================
#define N3_A      (64 * ESTR)
#define N3_B      (128 * ESTR)
#define N3_AB     (N3_A + N3_B)
#define N3_SMEM   (2 * N3_AB)

__global__ __launch_bounds__(256, 2) void gemm_norm64(
    const __half* __restrict__ A, const __half* __restrict__ B,
    const float* __restrict__ bias, __half* __restrict__ Zf)
{
    constexpr int K = HID, CH = K / 64, Ntot = LAT;
    extern __shared__ char smem[];
    const uint32_t sbase = smem_u32(smem);
    const int tid = threadIdx.x;
    const int bmg = blockIdx.y << 6;
    const int wid = tid >> 5, lane = tid & 31;
    const int wm = (wid & 1) << 5, wn = (wid >> 1) << 5;
    const int lrow = lane & 15, khalf = lane >> 4;

    float acc[2][4][4];
#pragma unroll
    for (int mt = 0; mt < 2; mt++)
#pragma unroll
        for (int nt = 0; nt < 4; nt++)
#pragma unroll
            for (int e = 0; e < 4; e++) acc[mt][nt][e] = 0.f;

    const int lra = tid >> 2, ka = (tid & 3) << 4;
    const int lrb = tid >> 1, kb = (tid & 1) << 5;

    auto load_chunk = [&](int c, int buf) {
        const uint32_t abase = sbase + (uint32_t)buf * N3_AB;
        const uint32_t bbase = abase + N3_A;
        const uint32_t oa = (uint32_t)lra * ESTR + (uint32_t)ka * 2;
        const char* ap = (const char*)(A + (size_t)(bmg + lra) * K + c * 64 + ka);
        cpa16(abase + oa,      ap);
        cpa16(abase + oa + 16, ap + 16);
        const uint32_t obp = (uint32_t)lrb * ESTR + (uint32_t)kb * 2;
        const char* bp = (const char*)(B + (size_t)lrb * K + c * 64 + kb);
#pragma unroll
        for (int q = 0; q < 4; q++)
            cpa16(bbase + obp + q * 16, bp + q * 16);
    };

    load_chunk(0, 0);
    CP_COMMIT();

    for (int c = 0; c < CH; c++) {
        CP_WAIT0();
        __syncthreads();
        if (c + 1 < CH) {
            load_chunk(c + 1, (c + 1) & 1);
            CP_COMMIT();
        }

        const uint32_t abase = sbase + (uint32_t)(c & 1) * N3_AB;
        const uint32_t bbase = abase + N3_A;
#pragma unroll
        for (int ks = 0; ks < 4; ks++) {
            const uint32_t koff = (uint32_t)ks * 32 + (uint32_t)khalf * 16;
            uint32_t a[2][4];
#pragma unroll
            for (int mt = 0; mt < 2; mt++)
                ldmx4(a[mt], abase + (uint32_t)(wm + mt * 16 + lrow) * ESTR + koff);
#pragma unroll
            for (int np = 0; np < 2; np++) {
                uint32_t t[4];
                ldmx4(t, bbase + (uint32_t)(wn + np * 16 + lrow) * ESTR + koff);
#pragma unroll
                for (int mt = 0; mt < 2; mt++) {
                    mma16816h(acc[mt][2*np+0], a[mt], t[0], t[2]);
                    mma16816h(acc[mt][2*np+1], a[mt], t[1], t[3]);
                }
            }
        }
    }

    const int r_in = lane >> 2;
    const int c_in = (lane & 3) << 1;

    float bias2[4][2];
#pragma unroll
    for (int nt = 0; nt < 4; nt++) {
        bias2[nt][0] = bias[wn + nt * 8 + c_in];
        bias2[nt][1] = bias[wn + nt * 8 + c_in + 1];
    }

    float ss[2][2] = {{0.f, 0.f}, {0.f, 0.f}};
#pragma unroll
    for (int mt = 0; mt < 2; mt++)
#pragma unroll
        for (int nt = 0; nt < 4; nt++) {
            acc[mt][nt][0] += bias2[nt][0];
            acc[mt][nt][1] += bias2[nt][1];
            acc[mt][nt][2] += bias2[nt][0];
            acc[mt][nt][3] += bias2[nt][1];
            ss[mt][0] = fmaf(acc[mt][nt][0], acc[mt][nt][0],
                        fmaf(acc[mt][nt][1], acc[mt][nt][1], ss[mt][0]));
            ss[mt][1] = fmaf(acc[mt][nt][2], acc[mt][nt][2],
                        fmaf(acc[mt][nt][3], acc[mt][nt][3], ss[mt][1]));
        }
#pragma unroll
    for (int m = 1; m <= 2; m <<= 1) {
#pragma unroll
        for (int mt = 0; mt < 2; mt++) {
            ss[mt][0] += __shfl_xor_sync(0xFFFFFFFFu, ss[mt][0], m);
            ss[mt][1] += __shfl_xor_sync(0xFFFFFFFFu, ss[mt][1], m);
        }
    }
    float* red  = (float*)smem;
    float* invp = red + 256;
    const int wcol = wid >> 1;
    __syncthreads();    // done with smem tiles before reuse as reduction space
    if ((lane & 3) == 0) {
#pragma unroll
        for (int mt = 0; mt < 2; mt++) {
            red[(wm + mt * 16 + r_in) * 4 + wcol]     = ss[mt][0];
            red[(wm + mt * 16 + r_in + 8) * 4 + wcol] = ss[mt][1];
        }
    }
    __syncthreads();
    if (tid < 64) {
        float s = red[tid * 4] + red[tid * 4 + 1] + red[tid * 4 + 2] + red[tid * 4 + 3];
        invp[tid] = 1.f / fmaxf(sqrtf(s), 1e-12f);
    }
    __syncthreads();
#pragma unroll
    for (int mt = 0; mt < 2; mt++) {
        const int rl = wm + mt * 16 + r_in;
        const float inv0 = invp[rl], inv1 = invp[rl + 8];
        const int r0 = bmg + rl;
#pragma unroll
        for (int nt = 0; nt < 4; nt++) {
            const int col = wn + nt * 8 + c_in;
            *(uint32_t*)(Zf + (size_t)r0 * Ntot + col) =
                packh2(acc[mt][nt][0] * inv0, acc[mt][nt][1] * inv0);
            *(uint32_t*)(Zf + (size_t)(r0 + 8) * Ntot + col) =
                packh2(acc[mt][nt][2] * inv1, acc[mt][nt][3] * inv1);
        }
    }
}

// ===========================================================================
// Final NT GEMM: C = Zx @ Zy^T, K=128, fp16. CTA = 128x512 strip (4 tiles),
// A loaded once, B double-buffered, 1 barrier/tile, fragment pipelining.
// 8 warps 4x2; 2 CTAs/SM.
// ===========================================================================
#define FSTR      272
#define F_A       0
#define F_B0      (128 * FSTR)
#define F_B1      (F_B0 + 128 * FSTR)
#define NTF_SMEM  (3 * 128 * FSTR)       // 104448 B

__global__ __launch_bounds__(256, 2) void gemm_nt_f16(
    const __half* __restrict__ ZA, const __half* __restrict__ ZB,
    float* __restrict__ C)
{
    extern __shared__ char smem[];
    const uint32_t sbase = smem_u32(smem);
    const int tid = threadIdx.x;
    const int bm = blockIdx.y << 7;
    const int bn = blockIdx.x << 9;          // 512-col strip (4 tiles)

    const int row  = tid >> 1;
    const int half = tid & 1;
    const uint32_t dof = (uint32_t)row * FSTR + (uint32_t)half * 128;

    // initial group: A + B0
    {
        const char* sa = (const char*)(ZA + (size_t)(bm + row) * LAT + half * 64);
        const char* sb = (const char*)(ZB + (size_t)(bn + row) * LAT + half * 64);
#pragma unroll
        for (int c = 0; c < 8; c++) {
            cpa16(sbase + F_A  + dof + c * 16, sa + c * 16);
            cpa16(sbase + F_B0 + dof + c * 16, sb + c * 16);
        }
    }
    CP_COMMIT();

    const int wid  = tid >> 5;
    const int lane = tid & 31;
    const int wm = (wid & 3) << 5;
    const int wn = (wid >> 2) << 6;
    const int lrow  = lane & 15;
    const int khalf = lane >> 4;
    const int r_in = lane >> 2;
    const int c_in = (lane & 3) << 1;

#pragma unroll
    for (int t = 0; t < 4; t++) {
        CP_WAIT0();
        __syncthreads();    // tile t ready; all warps done reading buf (t+1)&1
        if (t + 1 < 4) {
            const int brow = bn + (t + 1) * 128 + row;
            const char* sb = (const char*)(ZB + (size_t)brow * LAT + half * 64);
            const uint32_t bbuf = ((t + 1) & 1) ? F_B1 : F_B0;
#pragma unroll
            for (int c = 0; c < 8; c++)
                cpa16(sbase + bbuf + dof + c * 16, sb + c * 16);
            CP_COMMIT();
        }

        const uint32_t bbase = sbase + ((t & 1) ? F_B1 : F_B0);

        float acc[2][8][4];
#pragma unroll
        for (int mt = 0; mt < 2; mt++)
#pragma unroll
            for (int nt = 0; nt < 8; nt++)
#pragma unroll
                for (int e = 0; e < 4; e++) acc[mt][nt][e] = 0.f;

        // ---- fragment-pipelined mma over 8 k-steps ----
        uint32_t af[2][2][4], bf[2][4];
#pragma unroll
        for (int mt = 0; mt < 2; mt++)
            ldmx4(af[0][mt], sbase + F_A + (uint32_t)(wm + mt * 16 + lrow) * FSTR
                             + (uint32_t)khalf * 16);
        ldmx4(bf[0], bbase + (uint32_t)(wn + lrow) * FSTR + (uint32_t)khalf * 16);

#pragma unroll
        for (int ks = 0; ks < 8; ks++) {
            if (ks + 1 < 8) {
#pragma unroll
                for (int mt = 0; mt < 2; mt++)
                    ldmx4(af[(ks + 1) & 1][mt],
                          sbase + F_A + (uint32_t)(wm + mt * 16 + lrow) * FSTR
                                + (uint32_t)((ks + 1) * 32 + khalf * 16));
            }
#pragma unroll
            for (int np = 0; np < 4; np++) {
                const int idx = ks * 4 + np;
                if (idx + 1 < 32) {
                    const int nks = (idx + 1) >> 2, nnp = (idx + 1) & 3;
                    ldmx4(bf[(idx + 1) & 1],
                          bbase + (uint32_t)(wn + nnp * 16 + lrow) * FSTR
                                + (uint32_t)(nks * 32 + khalf * 16));
                }
                const uint32_t* bc = bf[idx & 1];
#pragma unroll
                for (int mt = 0; mt < 2; mt++) {
                    mma16816h(acc[mt][2*np+0], af[ks & 1][mt], bc[0], bc[2]);
                    mma16816h(acc[mt][2*np+1], af[ks & 1][mt], bc[1], bc[3]);
                }
            }
        }

        // per-tile epilogue
        const int r0 = bm + wm + r_in;
        const int c0 = bn + t * 128 + wn + c_in;
#pragma unroll
        for (int mt = 0; mt < 2; mt++) {
#pragma unroll
            for (int nt = 0; nt < 8; nt++) {
                float* p0 = C + (size_t)(r0 + mt * 16)     * NR + c0 + nt * 8;
                float* p1 = C + (size_t)(r0 + mt * 16 + 8) * NR + c0 + nt * 8;
                *(float2*)p0 = make_float2(acc[mt][nt][0], acc[mt][nt][1]);
                *(float2*)p1 = make_float2(acc[mt][nt][2], acc[mt][nt][3]);
            }
        }
    }
}

// ===========================================================================
extern "C" void kernel_launch(void* const* d_in, const int* in_sizes, int n_in,
                              void* d_out, int out_size)
{
    const float* x  = (const float*)d_in[0];
    const float* y  = (const float*)d_in[1];
    const float* W1 = (const float*)d_in[2];
    const float* b1 = (const float*)d_in[3];
    const float* W2 = (const float*)d_in[4];
    const float* b2 = (const float*)d_in[5];
    const float* W3 = (const float*)d_in[6];
    const float* b3 = (const float*)d_in[7];
    float* out = (float*)d_out;

    __half *H1, *H2, *Zf, *WT1, *WT2, *WT3;
    cudaGetSymbolAddress((void**)&H1,  g_H1);
    cudaGetSymbolAddress((void**)&H2,  g_H2);
    cudaGetSymbolAddress((void**)&Zf,  g_Zf);
    cudaGetSymbolAddress((void**)&WT1, g_WT1);
    cudaGetSymbolAddress((void**)&WT2, g_WT2);
    cudaGetSymbolAddress((void**)&WT3, g_WT3);

    cudaFuncSetAttribute(gemm_nt_f16, cudaFuncAttributeMaxDynamicSharedMemorySize, NTF_SMEM);
    cudaFuncSetAttribute(gemm_norm64, cudaFuncAttributeMaxDynamicSharedMemorySize, N3_SMEM);
    cudaFuncSetAttribute(gemm_enc<64,  true>,  cudaFuncAttributeMaxDynamicSharedMemorySize, ENC_SMEM);
    cudaFuncSetAttribute(gemm_enc<512, false>, cudaFuncAttributeMaxDynamicSharedMemorySize, ENC_SMEM);

    // launch 1, 2: weight prep
    prep_w13<<<(HID * DIM + LAT * HID + 255) / 256, 256>>>(W1, W3, WT1, WT3);
    prep_w2 <<<(HID * HID + 255) / 256, 256>>>(W2, WT2);

    // launch 3: layer 1 (fp32 x/y fused)
    dim3 g1(HID / 128, 2 * NR / 128);
    gemm_enc<64, true><<<g1, 256, ENC_SMEM>>>(x, y, WT1, b1, H1, HID);

    // launch 4 (profiled): layer 2
    dim3 g2(HID / 128, 2 * NR / 128);
    gemm_enc<512, false><<<g2, 256, ENC_SMEM>>>(H1, nullptr, WT2, b2, H2, HID);

    // launch 5: layer 3 + L2 norm
    dim3 g3(1, 2 * NR / 64);
    gemm_norm64<<<g3, 256, N3_SMEM>>>(H2, WT3, b3, Zf);

    // launch 6: similarity (4-tile strips, pipelined)
    dim3 g4(NR / 512, NR / 128);
    gemm_nt_f16<<<g4, 256, NTF_SMEM>>>(Zf, Zf + (size_t)NR * LAT, out);
}

// round 12
// speedup vs baseline: 1.1416x; 1.0814x over previous
#include <cuda_runtime.h>
#include <cuda_bf16.h>
#include <cuda_fp16.h>
#include <math.h>
#include <cstdint>

#define NR   8192
#define DIM  64
#define HID  512
#define LAT  128

// Scratch (device globals — allocation-free per harness rules)
__device__ __half g_H1[2 * NR * HID];    // 16 MB
__device__ __half g_H2[2 * NR * HID];    // 16 MB
__device__ __half g_Zf[2 * NR * LAT];    //  4 MB
__device__ __half g_WT1[HID * DIM];
__device__ __half g_WT2[HID * HID];
__device__ __half g_WT3[LAT * HID];

// ===========================================================================
// helpers
// ===========================================================================
__device__ __forceinline__ uint32_t smem_u32(const void* p) {
    uint32_t a;
    asm("{ .reg .u64 t; cvta.to.shared.u64 t, %1; cvt.u32.u64 %0, t; }"
        : "=r"(a) : "l"(p));
    return a;
}
__device__ __forceinline__ void ldmx4(uint32_t* r, uint32_t addr) {
    asm volatile("ldmatrix.sync.aligned.m8n8.x4.shared.b16 {%0,%1,%2,%3}, [%4];"
                 : "=r"(r[0]), "=r"(r[1]), "=r"(r[2]), "=r"(r[3]) : "r"(addr));
}
__device__ __forceinline__ void mma16816h(float* d, const uint32_t* a,
                                          uint32_t b0, uint32_t b1) {
    asm volatile(
        "mma.sync.aligned.m16n8k16.row.col.f32.f16.f16.f32 "
        "{%0,%1,%2,%3}, {%4,%5,%6,%7}, {%8,%9}, {%0,%1,%2,%3};"
        : "+f"(d[0]), "+f"(d[1]), "+f"(d[2]), "+f"(d[3])
        : "r"(a[0]), "r"(a[1]), "r"(a[2]), "r"(a[3]), "r"(b0), "r"(b1));
}
__device__ __forceinline__ void cpa16(uint32_t dst, const void* src) {
    asm volatile("cp.async.cg.shared.global [%0], [%1], 16;"
                 :: "r"(dst), "l"(src));
}
#define CP_COMMIT() asm volatile("cp.async.commit_group;")
#define CP_WAIT0()  asm volatile("cp.async.wait_group 0;" ::: "memory")

__device__ __forceinline__ uint32_t packh2(float a, float b) {
    uint32_t r;
    asm("cvt.rn.f16x2.f32 %0, %1, %2;" : "=r"(r) : "f"(b), "f"(a));
    return r;
}

// ===========================================================================
// prep kernels (2 launches so layer2 lands at captured launch #4)
// ===========================================================================
__global__ void prep_w2(const float* __restrict__ W,
                        __half* __restrict__ WT) {
    int idx = blockIdx.x * blockDim.x + threadIdx.x;
    if (idx >= HID * HID) return;
    int n = idx / HID, k = idx - n * HID;
    WT[idx] = __float2half(W[(size_t)k * HID + n]);
}
__global__ void prep_w13(const float* __restrict__ W1s, const float* __restrict__ W3s,
                         __half* __restrict__ WT1d, __half* __restrict__ WT3d) {
    int idx = blockIdx.x * blockDim.x + threadIdx.x;
    if (idx < HID * DIM) {
        int n = idx / DIM, k = idx - n * DIM;
        WT1d[idx] = __float2half(W1s[(size_t)k * HID + n]);
    } else if (idx < HID * DIM + LAT * HID) {
        int j = idx - HID * DIM;
        int n = j / HID, k = j - n * HID;
        WT3d[j] = __float2half(W3s[(size_t)k * LAT + n]);
    }
}

// ===========================================================================
// Encoder mma GEMM (layers 1,2): 512 threads, 16 warps (4x4), warp tile
// 32x32, CTA 128x128, BK=64 double-buffered, 2 CTAs/SM (32 warps/SM).
// ===========================================================================
#define ESTR      144
#define ET        (128 * ESTR)
#define ENC_SMEM  (4 * ET)               // 73728

template<int K, bool A_FP32>
__global__ __launch_bounds__(512, 2) void gemm_enc(
    const void* __restrict__ Ax, const void* __restrict__ Ay,
    const __half* __restrict__ B,
    const float* __restrict__ bias,
    __half* __restrict__ Cf, int Ntot)
{
    constexpr int CH = K / 64;
    extern __shared__ char smem[];
    const uint32_t sbase = smem_u32(smem);
    const int tid = threadIdx.x;
    const int bmg = blockIdx.y << 7, bn = blockIdx.x << 7;
    const int wid = tid >> 5, lane = tid & 31;
    const int wm = (wid & 3) << 5, wn = (wid >> 2) << 5;
    const int lrow = lane & 15, khalf = lane >> 4;

    const float* Af32 = nullptr;
    const __half* Af16 = nullptr;
    int bm;
    if (A_FP32) {
        Af32 = (bmg < NR) ? (const float*)Ax : (const float*)Ay;
        bm = (bmg < NR) ? bmg : bmg - NR;
    } else {
        Af16 = (const __half*)Ax;
        bm = bmg;
    }

    float acc[2][4][4];
#pragma unroll
    for (int mt = 0; mt < 2; mt++)
#pragma unroll
        for (int nt = 0; nt < 4; nt++)
#pragma unroll
            for (int e = 0; e < 4; e++) acc[mt][nt][e] = 0.f;

    const int lr  = tid >> 2;           // 0..127
    const int ksg = (tid & 3) << 4;     // 0,16,32,48 elements

    auto load_chunk = [&](int c, int buf) {
        const uint32_t abase = sbase + (uint32_t)(buf * 2) * ET;
        const uint32_t bbase = abase + ET;
        const uint32_t ob = (uint32_t)lr * ESTR + (uint32_t)ksg * 2;
        if (A_FP32) {
            const float* ap = Af32 + (size_t)(bm + lr) * K + c * 64 + ksg;
#pragma unroll
            for (int q = 0; q < 2; q++) {
                float4 f0 = *(const float4*)(ap + q * 8);
                float4 f1 = *(const float4*)(ap + q * 8 + 4);
                uint4 v;
                v.x = packh2(f0.x, f0.y); v.y = packh2(f0.z, f0.w);
                v.z = packh2(f1.x, f1.y); v.w = packh2(f1.z, f1.w);
                *(uint4*)(smem + (abase - sbase) + ob + q * 16) = v;
            }
        } else {
            const char* ap = (const char*)(Af16 + (size_t)(bm + lr) * K + c * 64 + ksg);
            cpa16(abase + ob,      ap);
            cpa16(abase + ob + 16, ap + 16);
        }
        const char* bp = (const char*)(B + (size_t)(bn + lr) * K + c * 64 + ksg);
        cpa16(bbase + ob,      bp);
        cpa16(bbase + ob + 16, bp + 16);
    };

    load_chunk(0, 0);
    CP_COMMIT();

    for (int c = 0; c < CH; c++) {
        CP_WAIT0();
        __syncthreads();
        if (c + 1 < CH) {
            load_chunk(c + 1, (c + 1) & 1);
            CP_COMMIT();
        }

        const uint32_t abase = sbase + (uint32_t)((c & 1) * 2) * ET;
        const uint32_t bbase = abase + ET;
#pragma unroll
        for (int ks = 0; ks < 4; ks++) {
            const uint32_t koff = (uint32_t)ks * 32 + (uint32_t)khalf * 16;
            uint32_t a[2][4];
#pragma unroll
            for (int mt = 0; mt < 2; mt++)
                ldmx4(a[mt], abase + (uint32_t)(wm + mt * 16 + lrow) * ESTR + koff);
#pragma unroll
            for (int np = 0; np < 2; np++) {
                uint32_t t[4];
                ldmx4(t, bbase + (uint32_t)(wn + np * 16 + lrow) * ESTR + koff);
#pragma unroll
                for (int mt = 0; mt < 2; mt++) {
                    mma16816h(acc[mt][2*np+0], a[mt], t[0], t[2]);
                    mma16816h(acc[mt][2*np+1], a[mt], t[1], t[3]);
                }
            }
        }
    }

    const int r_in = lane >> 2;
    const int c_in = (lane & 3) << 1;

#pragma unroll
    for (int mt = 0; mt < 2; mt++) {
        const int r0 = bmg + wm + mt * 16 + r_in;
#pragma unroll
        for (int nt = 0; nt < 4; nt++) {
            const int col = bn + wn + nt * 8 + c_in;
            const float b0 = bias[col], b1 = bias[col + 1];
            float o0 = fmaxf(acc[mt][nt][0] + b0, 0.f);
            float o1 = fmaxf(acc[mt][nt][1] + b1, 0.f);
            float o2 = fmaxf(acc[mt][nt][2] + b0, 0.f);
            float o3 = fmaxf(acc[mt][nt][3] + b1, 0.f);
            *(uint32_t*)(Cf + (size_t)r0 * Ntot + col)       = packh2(o0, o1);
            *(uint32_t*)(Cf + (size_t)(r0 + 8) * Ntot + col) = packh2(o2, o3);
        }
    }
}

// ===========================================================================
// Layer 3 + L2 norm: CTA 64x128, K=512 (BK=64, double-buffered), 256 thr,
// 8 warps (2 M x 4 N), grid 512, 2 CTAs/SM. (round-10/11 validated)
// ===========================================================================
#define N3_A      (64 * ESTR)
#define N3_B      (128 * ESTR)
#define N3_AB     (N3_A + N3_B)
#define N3_SMEM   (2 * N3_AB)

__global__ __launch_bounds__(256, 2) void gemm_norm64(
    const __half* __restrict__ A, const __half* __restrict__ B,
    const float* __restrict__ bias, __half* __restrict__ Zf)
{
    constexpr int K = HID, CH = K / 64, Ntot = LAT;
    extern __shared__ char smem[];
    const uint32_t sbase = smem_u32(smem);
    const int tid = threadIdx.x;
    const int bmg = blockIdx.y << 6;
    const int wid = tid >> 5, lane = tid & 31;
    const int wm = (wid & 1) << 5, wn = (wid >> 1) << 5;
    const int lrow = lane & 15, khalf = lane >> 4;

    float acc[2][4][4];
#pragma unroll
    for (int mt = 0; mt < 2; mt++)
#pragma unroll
        for (int nt = 0; nt < 4; nt++)
#pragma unroll
            for (int e = 0; e < 4; e++) acc[mt][nt][e] = 0.f;

    const int lra = tid >> 2, ka = (tid & 3) << 4;
    const int lrb = tid >> 1, kb = (tid & 1) << 5;

    auto load_chunk = [&](int c, int buf) {
        const uint32_t abase = sbase + (uint32_t)buf * N3_AB;
        const uint32_t bbase = abase + N3_A;
        const uint32_t oa = (uint32_t)lra * ESTR + (uint32_t)ka * 2;
        const char* ap = (const char*)(A + (size_t)(bmg + lra) * K + c * 64 + ka);
        cpa16(abase + oa,      ap);
        cpa16(abase + oa + 16, ap + 16);
        const uint32_t obp = (uint32_t)lrb * ESTR + (uint32_t)kb * 2;
        const char* bp = (const char*)(B + (size_t)lrb * K + c * 64 + kb);
#pragma unroll
        for (int q = 0; q < 4; q++)
            cpa16(bbase + obp + q * 16, bp + q * 16);
    };

    load_chunk(0, 0);
    CP_COMMIT();

    for (int c = 0; c < CH; c++) {
        CP_WAIT0();
        __syncthreads();
        if (c + 1 < CH) {
            load_chunk(c + 1, (c + 1) & 1);
            CP_COMMIT();
        }

        const uint32_t abase = sbase + (uint32_t)(c & 1) * N3_AB;
        const uint32_t bbase = abase + N3_A;
#pragma unroll
        for (int ks = 0; ks < 4; ks++) {
            const uint32_t koff = (uint32_t)ks * 32 + (uint32_t)khalf * 16;
            uint32_t a[2][4];
#pragma unroll
            for (int mt = 0; mt < 2; mt++)
                ldmx4(a[mt], abase + (uint32_t)(wm + mt * 16 + lrow) * ESTR + koff);
#pragma unroll
            for (int np = 0; np < 2; np++) {
                uint32_t t[4];
                ldmx4(t, bbase + (uint32_t)(wn + np * 16 + lrow) * ESTR + koff);
#pragma unroll
                for (int mt = 0; mt < 2; mt++) {
                    mma16816h(acc[mt][2*np+0], a[mt], t[0], t[2]);
                    mma16816h(acc[mt][2*np+1], a[mt], t[1], t[3]);
                }
            }
        }
    }

    const int r_in = lane >> 2;
    const int c_in = (lane & 3) << 1;

    float bias2[4][2];
#pragma unroll
    for (int nt = 0; nt < 4; nt++) {
        bias2[nt][0] = bias[wn + nt * 8 + c_in];
        bias2[nt][1] = bias[wn + nt * 8 + c_in + 1];
    }

    float ss[2][2] = {{0.f, 0.f}, {0.f, 0.f}};
#pragma unroll
    for (int mt = 0; mt < 2; mt++)
#pragma unroll
        for (int nt = 0; nt < 4; nt++) {
            acc[mt][nt][0] += bias2[nt][0];
            acc[mt][nt][1] += bias2[nt][1];
            acc[mt][nt][2] += bias2[nt][0];
            acc[mt][nt][3] += bias2[nt][1];
            ss[mt][0] = fmaf(acc[mt][nt][0], acc[mt][nt][0],
                        fmaf(acc[mt][nt][1], acc[mt][nt][1], ss[mt][0]));
            ss[mt][1] = fmaf(acc[mt][nt][2], acc[mt][nt][2],
                        fmaf(acc[mt][nt][3], acc[mt][nt][3], ss[mt][1]));
        }
#pragma unroll
    for (int m = 1; m <= 2; m <<= 1) {
#pragma unroll
        for (int mt = 0; mt < 2; mt++) {
            ss[mt][0] += __shfl_xor_sync(0xFFFFFFFFu, ss[mt][0], m);
            ss[mt][1] += __shfl_xor_sync(0xFFFFFFFFu, ss[mt][1], m);
        }
    }
    float* red  = (float*)smem;
    float* invp = red + 256;
    const int wcol = wid >> 1;
    __syncthreads();
    if ((lane & 3) == 0) {
#pragma unroll
        for (int mt = 0; mt < 2; mt++) {
            red[(wm + mt * 16 + r_in) * 4 + wcol]     = ss[mt][0];
            red[(wm + mt * 16 + r_in + 8) * 4 + wcol] = ss[mt][1];
        }
    }
    __syncthreads();
    if (tid < 64) {
        float s = red[tid * 4] + red[tid * 4 + 1] + red[tid * 4 + 2] + red[tid * 4 + 3];
        invp[tid] = 1.f / fmaxf(sqrtf(s), 1e-12f);
    }
    __syncthreads();
#pragma unroll
    for (int mt = 0; mt < 2; mt++) {
        const int rl = wm + mt * 16 + r_in;
        const float inv0 = invp[rl], inv1 = invp[rl + 8];
        const int r0 = bmg + rl;
#pragma unroll
        for (int nt = 0; nt < 4; nt++) {
            const int col = wn + nt * 8 + c_in;
            *(uint32_t*)(Zf + (size_t)r0 * Ntot + col) =
                packh2(acc[mt][nt][0] * inv0, acc[mt][nt][1] * inv0);
            *(uint32_t*)(Zf + (size_t)(r0 + 8) * Ntot + col) =
                packh2(acc[mt][nt][2] * inv1, acc[mt][nt][3] * inv1);
        }
    }
}

// ===========================================================================
// Final NT GEMM: C = Zx @ Zy^T, K=128, fp16. CTA = 128x512 strip (4 tiles),
// 512 threads, 16 warps (4x4), warp tile 32x32. A once, B double-buffered,
// 1 barrier/tile. 2 CTAs/SM (32 warps/SM).
// ===========================================================================
#define FSTR      272
#define F_A       0
#define F_B0      (128 * FSTR)
#define F_B1      (F_B0 + 128 * FSTR)
#define NTF_SMEM  (3 * 128 * FSTR)       // 104448 B

__global__ __launch_bounds__(512, 2) void gemm_nt_f16(
    const __half* __restrict__ ZA, const __half* __restrict__ ZB,
    float* __restrict__ C)
{
    extern __shared__ char smem[];
    const uint32_t sbase = smem_u32(smem);
    const int tid = threadIdx.x;
    const int bm = blockIdx.y << 7;
    const int bn = blockIdx.x << 9;          // 512-col strip (4 tiles)

    const int row = tid >> 2;                // 0..127
    const int q   = tid & 3;                 // 64 B per thread
    const uint32_t dof = (uint32_t)row * FSTR + (uint32_t)q * 64;

    // initial group: A + B0
    {
        const char* sa = (const char*)(ZA + (size_t)(bm + row) * LAT + q * 32);
        const char* sb = (const char*)(ZB + (size_t)(bn + row) * LAT + q * 32);
#pragma unroll
        for (int c = 0; c < 4; c++) {
            cpa16(sbase + F_A  + dof + c * 16, sa + c * 16);
            cpa16(sbase + F_B0 + dof + c * 16, sb + c * 16);
        }
    }
    CP_COMMIT();

    const int wid  = tid >> 5;
    const int lane = tid & 31;
    const int wm = (wid & 3) << 5;           // 0..96
    const int wn = (wid >> 2) << 5;          // 0..96
    const int lrow  = lane & 15;
    const int khalf = lane >> 4;
    const int r_in = lane >> 2;
    const int c_in = (lane & 3) << 1;

#pragma unroll
    for (int t = 0; t < 4; t++) {
        CP_WAIT0();
        __syncthreads();    // tile t ready; all warps done reading buf (t+1)&1
        if (t + 1 < 4) {
            const int brow = bn + (t + 1) * 128 + row;
            const char* sb = (const char*)(ZB + (size_t)brow * LAT + q * 32);
            const uint32_t bbuf = ((t + 1) & 1) ? F_B1 : F_B0;
#pragma unroll
            for (int c = 0; c < 4; c++)
                cpa16(sbase + bbuf + dof + c * 16, sb + c * 16);
            CP_COMMIT();
        }

        const uint32_t bbase = sbase + ((t & 1) ? F_B1 : F_B0);

        float acc[2][4][4];
#pragma unroll
        for (int mt = 0; mt < 2; mt++)
#pragma unroll
            for (int nt = 0; nt < 4; nt++)
#pragma unroll
                for (int e = 0; e < 4; e++) acc[mt][nt][e] = 0.f;

#pragma unroll
        for (int ks = 0; ks < 8; ks++) {
            const uint32_t koff = (uint32_t)ks * 32 + (uint32_t)khalf * 16;
            uint32_t a[2][4];
#pragma unroll
            for (int mt = 0; mt < 2; mt++)
                ldmx4(a[mt], sbase + F_A + (uint32_t)(wm + mt * 16 + lrow) * FSTR + koff);
#pragma unroll
            for (int np = 0; np < 2; np++) {
                uint32_t b[4];
                ldmx4(b, bbase + (uint32_t)(wn + np * 16 + lrow) * FSTR + koff);
#pragma unroll
                for (int mt = 0; mt < 2; mt++) {
                    mma16816h(acc[mt][2*np+0], a[mt], b[0], b[2]);
                    mma16816h(acc[mt][2*np+1], a[mt], b[1], b[3]);
                }
            }
        }

        // per-tile epilogue
        const int r0 = bm + wm + r_in;
        const int c0 = bn + t * 128 + wn + c_in;
#pragma unroll
        for (int mt = 0; mt < 2; mt++) {
#pragma unroll
            for (int nt = 0; nt < 4; nt++) {
                float* p0 = C + (size_t)(r0 + mt * 16)     * NR + c0 + nt * 8;
                float* p1 = C + (size_t)(r0 + mt * 16 + 8) * NR + c0 + nt * 8;
                *(float2*)p0 = make_float2(acc[mt][nt][0], acc[mt][nt][1]);
                *(float2*)p1 = make_float2(acc[mt][nt][2], acc[mt][nt][3]);
            }
        }
    }
}

// ===========================================================================
extern "C" void kernel_launch(void* const* d_in, const int* in_sizes, int n_in,
                              void* d_out, int out_size)
{
    const float* x  = (const float*)d_in[0];
    const float* y  = (const float*)d_in[1];
    const float* W1 = (const float*)d_in[2];
    const float* b1 = (const float*)d_in[3];
    const float* W2 = (const float*)d_in[4];
    const float* b2 = (const float*)d_in[5];
    const float* W3 = (const float*)d_in[6];
    const float* b3 = (const float*)d_in[7];
    float* out = (float*)d_out;

    __half *H1, *H2, *Zf, *WT1, *WT2, *WT3;
    cudaGetSymbolAddress((void**)&H1,  g_H1);
    cudaGetSymbolAddress((void**)&H2,  g_H2);
    cudaGetSymbolAddress((void**)&Zf,  g_Zf);
    cudaGetSymbolAddress((void**)&WT1, g_WT1);
    cudaGetSymbolAddress((void**)&WT2, g_WT2);
    cudaGetSymbolAddress((void**)&WT3, g_WT3);

    cudaFuncSetAttribute(gemm_nt_f16, cudaFuncAttributeMaxDynamicSharedMemorySize, NTF_SMEM);
    cudaFuncSetAttribute(gemm_norm64, cudaFuncAttributeMaxDynamicSharedMemorySize, N3_SMEM);
    cudaFuncSetAttribute(gemm_enc<64,  true>,  cudaFuncAttributeMaxDynamicSharedMemorySize, ENC_SMEM);
    cudaFuncSetAttribute(gemm_enc<512, false>, cudaFuncAttributeMaxDynamicSharedMemorySize, ENC_SMEM);

    // launch 1, 2: weight prep
    prep_w13<<<(HID * DIM + LAT * HID + 255) / 256, 256>>>(W1, W3, WT1, WT3);
    prep_w2 <<<(HID * HID + 255) / 256, 256>>>(W2, WT2);

    // launch 3: layer 1 (fp32 x/y fused)
    dim3 g1(HID / 128, 2 * NR / 128);
    gemm_enc<64, true><<<g1, 512, ENC_SMEM>>>(x, y, WT1, b1, H1, HID);

    // launch 4 (profiled): layer 2
    dim3 g2(HID / 128, 2 * NR / 128);
    gemm_enc<512, false><<<g2, 512, ENC_SMEM>>>(H1, nullptr, WT2, b2, H2, HID);

    // launch 5: layer 3 + L2 norm
    dim3 g3(1, 2 * NR / 64);
    gemm_norm64<<<g3, 256, N3_SMEM>>>(H2, WT3, b3, Zf);

    // launch 6: similarity (4-tile strips, 512 threads)
    dim3 g4(NR / 512, NR / 128);
    gemm_nt_f16<<<g4, 512, NTF_SMEM>>>(Zf, Zf + (size_t)NR * LAT, out);
}

// round 13
// speedup vs baseline: 1.1680x; 1.0232x over previous
#include <cuda_runtime.h>
#include <cuda_bf16.h>
#include <cuda_fp16.h>
#include <math.h>
#include <cstdint>

#define NR   8192
#define DIM  64
#define HID  512
#define LAT  128

// Scratch (device globals — allocation-free per harness rules)
__device__ __half g_H1[2 * NR * HID];    // 16 MB
__device__ __half g_H2[2 * NR * HID];    // 16 MB
__device__ __half g_Zf[2 * NR * LAT];    //  4 MB
__device__ __half g_WT1[HID * DIM];
__device__ __half g_WT2[HID * HID];
__device__ __half g_WT3[LAT * HID];

// ===========================================================================
// helpers
// ===========================================================================
__device__ __forceinline__ uint32_t smem_u32(const void* p) {
    uint32_t a;
    asm("{ .reg .u64 t; cvta.to.shared.u64 t, %1; cvt.u32.u64 %0, t; }"
        : "=r"(a) : "l"(p));
    return a;
}
__device__ __forceinline__ void ldmx4(uint32_t* r, uint32_t addr) {
    asm volatile("ldmatrix.sync.aligned.m8n8.x4.shared.b16 {%0,%1,%2,%3}, [%4];"
                 : "=r"(r[0]), "=r"(r[1]), "=r"(r[2]), "=r"(r[3]) : "r"(addr));
}
__device__ __forceinline__ void mma16816h(float* d, const uint32_t* a,
                                          uint32_t b0, uint32_t b1) {
    asm volatile(
        "mma.sync.aligned.m16n8k16.row.col.f32.f16.f16.f32 "
        "{%0,%1,%2,%3}, {%4,%5,%6,%7}, {%8,%9}, {%0,%1,%2,%3};"
        : "+f"(d[0]), "+f"(d[1]), "+f"(d[2]), "+f"(d[3])
        : "r"(a[0]), "r"(a[1]), "r"(a[2]), "r"(a[3]), "r"(b0), "r"(b1));
}
__device__ __forceinline__ void cpa16(uint32_t dst, const void* src) {
    asm volatile("cp.async.cg.shared.global [%0], [%1], 16;"
                 :: "r"(dst), "l"(src));
}
#define CP_COMMIT() asm volatile("cp.async.commit_group;")
#define CP_WAIT0()  asm volatile("cp.async.wait_group 0;" ::: "memory")

__device__ __forceinline__ uint32_t packh2(float a, float b) {
    uint32_t r;
    asm("cvt.rn.f16x2.f32 %0, %1, %2;" : "=r"(r) : "f"(b), "f"(a));
    return r;
}

// ===========================================================================
// prep kernels (2 launches so layer2 lands at captured launch #4)
// ===========================================================================
__global__ void prep_w2(const float* __restrict__ W,
                        __half* __restrict__ WT) {
    int idx = blockIdx.x * blockDim.x + threadIdx.x;
    if (idx >= HID * HID) return;
    int n = idx / HID, k = idx - n * HID;
    WT[idx] = __float2half(W[(size_t)k * HID + n]);
}
__global__ void prep_w13(const float* __restrict__ W1s, const float* __restrict__ W3s,
                         __half* __restrict__ WT1d, __half* __restrict__ WT3d) {
    int idx = blockIdx.x * blockDim.x + threadIdx.x;
    if (idx < HID * DIM) {
        int n = idx / DIM, k = idx - n * DIM;
        WT1d[idx] = __float2half(W1s[(size_t)k * HID + n]);
    } else if (idx < HID * DIM + LAT * HID) {
        int j = idx - HID * DIM;
        int n = j / HID, k = j - n * HID;
        WT3d[j] = __float2half(W3s[(size_t)k * LAT + n]);
    }
}

// ===========================================================================
// Encoder mma GEMM (layers 1,2): 512 threads, 16 warps (4x4), warp tile
// 32x32, CTA 128x128, BK=64 double-buffered, 2 CTAs/SM. (round-12 validated)
// ===========================================================================
#define ESTR      144
#define ET        (128 * ESTR)
#define ENC_SMEM  (4 * ET)               // 73728

template<int K, bool A_FP32>
__global__ __launch_bounds__(512, 2) void gemm_enc(
    const void* __restrict__ Ax, const void* __restrict__ Ay,
    const __half* __restrict__ B,
    const float* __restrict__ bias,
    __half* __restrict__ Cf, int Ntot)
{
    constexpr int CH = K / 64;
    extern __shared__ char smem[];
    const uint32_t sbase = smem_u32(smem);
    const int tid = threadIdx.x;
    const int bmg = blockIdx.y << 7, bn = blockIdx.x << 7;
    const int wid = tid >> 5, lane = tid & 31;
    const int wm = (wid & 3) << 5, wn = (wid >> 2) << 5;
    const int lrow = lane & 15, khalf = lane >> 4;

    const float* Af32 = nullptr;
    const __half* Af16 = nullptr;
    int bm;
    if (A_FP32) {
        Af32 = (bmg < NR) ? (const float*)Ax : (const float*)Ay;
        bm = (bmg < NR) ? bmg : bmg - NR;
    } else {
        Af16 = (const __half*)Ax;
        bm = bmg;
    }

    float acc[2][4][4];
#pragma unroll
    for (int mt = 0; mt < 2; mt++)
#pragma unroll
        for (int nt = 0; nt < 4; nt++)
#pragma unroll
            for (int e = 0; e < 4; e++) acc[mt][nt][e] = 0.f;

    const int lr  = tid >> 2;           // 0..127
    const int ksg = (tid & 3) << 4;     // 0,16,32,48 elements

    auto load_chunk = [&](int c, int buf) {
        const uint32_t abase = sbase + (uint32_t)(buf * 2) * ET;
        const uint32_t bbase = abase + ET;
        const uint32_t ob = (uint32_t)lr * ESTR + (uint32_t)ksg * 2;
        if (A_FP32) {
            const float* ap = Af32 + (size_t)(bm + lr) * K + c * 64 + ksg;
#pragma unroll
            for (int q = 0; q < 2; q++) {
                float4 f0 = *(const float4*)(ap + q * 8);
                float4 f1 = *(const float4*)(ap + q * 8 + 4);
                uint4 v;
                v.x = packh2(f0.x, f0.y); v.y = packh2(f0.z, f0.w);
                v.z = packh2(f1.x, f1.y); v.w = packh2(f1.z, f1.w);
                *(uint4*)(smem + (abase - sbase) + ob + q * 16) = v;
            }
        } else {
            const char* ap = (const char*)(Af16 + (size_t)(bm + lr) * K + c * 64 + ksg);
            cpa16(abase + ob,      ap);
            cpa16(abase + ob + 16, ap + 16);
        }
        const char* bp = (const char*)(B + (size_t)(bn + lr) * K + c * 64 + ksg);
        cpa16(bbase + ob,      bp);
        cpa16(bbase + ob + 16, bp + 16);
    };

    load_chunk(0, 0);
    CP_COMMIT();

    for (int c = 0; c < CH; c++) {
        CP_WAIT0();
        __syncthreads();
        if (c + 1 < CH) {
            load_chunk(c + 1, (c + 1) & 1);
            CP_COMMIT();
        }

        const uint32_t abase = sbase + (uint32_t)((c & 1) * 2) * ET;
        const uint32_t bbase = abase + ET;
#pragma unroll
        for (int ks = 0; ks < 4; ks++) {
            const uint32_t koff = (uint32_t)ks * 32 + (uint32_t)khalf * 16;
            uint32_t a[2][4];
#pragma unroll
            for (int mt = 0; mt < 2; mt++)
                ldmx4(a[mt], abase + (uint32_t)(wm + mt * 16 + lrow) * ESTR + koff);
#pragma unroll
            for (int np = 0; np < 2; np++) {
                uint32_t t[4];
                ldmx4(t, bbase + (uint32_t)(wn + np * 16 + lrow) * ESTR + koff);
#pragma unroll
                for (int mt = 0; mt < 2; mt++) {
                    mma16816h(acc[mt][2*np+0], a[mt], t[0], t[2]);
                    mma16816h(acc[mt][2*np+1], a[mt], t[1], t[3]);
                }
            }
        }
    }

    const int r_in = lane >> 2;
    const int c_in = (lane & 3) << 1;

#pragma unroll
    for (int mt = 0; mt < 2; mt++) {
        const int r0 = bmg + wm + mt * 16 + r_in;
#pragma unroll
        for (int nt = 0; nt < 4; nt++) {
            const int col = bn + wn + nt * 8 + c_in;
            const float b0 = bias[col], b1 = bias[col + 1];
            float o0 = fmaxf(acc[mt][nt][0] + b0, 0.f);
            float o1 = fmaxf(acc[mt][nt][1] + b1, 0.f);
            float o2 = fmaxf(acc[mt][nt][2] + b0, 0.f);
            float o3 = fmaxf(acc[mt][nt][3] + b1, 0.f);
            *(uint32_t*)(Cf + (size_t)r0 * Ntot + col)       = packh2(o0, o1);
            *(uint32_t*)(Cf + (size_t)(r0 + 8) * Ntot + col) = packh2(o2, o3);
        }
    }
}

// ===========================================================================
// Layer 3 + L2 norm: CTA 64x128, K=512 (BK=64, double-buffered), 256 thr,
// 8 warps (2 M x 4 N), grid 512, NOW 3 CTAs/SM (tail fix).
// ===========================================================================
#define N3_A      (64 * ESTR)
#define N3_B      (128 * ESTR)
#define N3_AB     (N3_A + N3_B)
#define N3_SMEM   (2 * N3_AB)

__global__ __launch_bounds__(256, 3) void gemm_norm64(
    const __half* __restrict__ A, const __half* __restrict__ B,
    const float* __restrict__ bias, __half* __restrict__ Zf)
{
    constexpr int K = HID, CH = K / 64, Ntot = LAT;
    extern __shared__ char smem[];
    const uint32_t sbase = smem_u32(smem);
    const int tid = threadIdx.x;
    const int bmg = blockIdx.y << 6;
    const int wid = tid >> 5, lane = tid & 31;
    const int wm = (wid & 1) << 5, wn = (wid >> 1) << 5;
    const int lrow = lane & 15, khalf = lane >> 4;

    float acc[2][4][4];
#pragma unroll
    for (int mt = 0; mt < 2; mt++)
#pragma unroll
        for (int nt = 0; nt < 4; nt++)
#pragma unroll
            for (int e = 0; e < 4; e++) acc[mt][nt][e] = 0.f;

    const int lra = tid >> 2, ka = (tid & 3) << 4;
    const int lrb = tid >> 1, kb = (tid & 1) << 5;

    auto load_chunk = [&](int c, int buf) {
        const uint32_t abase = sbase + (uint32_t)buf * N3_AB;
        const uint32_t bbase = abase + N3_A;
        const uint32_t oa = (uint32_t)lra * ESTR + (uint32_t)ka * 2;
        const char* ap = (const char*)(A + (size_t)(bmg + lra) * K + c * 64 + ka);
        cpa16(abase + oa,      ap);
        cpa16(abase + oa + 16, ap + 16);
        const uint32_t obp = (uint32_t)lrb * ESTR + (uint32_t)kb * 2;
        const char* bp = (const char*)(B + (size_t)lrb * K + c * 64 + kb);
#pragma unroll
        for (int q = 0; q < 4; q++)
            cpa16(bbase + obp + q * 16, bp + q * 16);
    };

    load_chunk(0, 0);
    CP_COMMIT();

    for (int c = 0; c < CH; c++) {
        CP_WAIT0();
        __syncthreads();
        if (c + 1 < CH) {
            load_chunk(c + 1, (c + 1) & 1);
            CP_COMMIT();
        }

        const uint32_t abase = sbase + (uint32_t)(c & 1) * N3_AB;
        const uint32_t bbase = abase + N3_A;
#pragma unroll
        for (int ks = 0; ks < 4; ks++) {
            const uint32_t koff = (uint32_t)ks * 32 + (uint32_t)khalf * 16;
            uint32_t a[2][4];
#pragma unroll
            for (int mt = 0; mt < 2; mt++)
                ldmx4(a[mt], abase + (uint32_t)(wm + mt * 16 + lrow) * ESTR + koff);
#pragma unroll
            for (int np = 0; np < 2; np++) {
                uint32_t t[4];
                ldmx4(t, bbase + (uint32_t)(wn + np * 16 + lrow) * ESTR + koff);
#pragma unroll
                for (int mt = 0; mt < 2; mt++) {
                    mma16816h(acc[mt][2*np+0], a[mt], t[0], t[2]);
                    mma16816h(acc[mt][2*np+1], a[mt], t[1], t[3]);
                }
            }
        }
    }

    const int r_in = lane >> 2;
    const int c_in = (lane & 3) << 1;

    float bias2[4][2];
#pragma unroll
    for (int nt = 0; nt < 4; nt++) {
        bias2[nt][0] = bias[wn + nt * 8 + c_in];
        bias2[nt][1] = bias[wn + nt * 8 + c_in + 1];
    }

    float ss[2][2] = {{0.f, 0.f}, {0.f, 0.f}};
#pragma unroll
    for (int mt = 0; mt < 2; mt++)
#pragma unroll
        for (int nt = 0; nt < 4; nt++) {
            acc[mt][nt][0] += bias2[nt][0];
            acc[mt][nt][1] += bias2[nt][1];
            acc[mt][nt][2] += bias2[nt][0];
            acc[mt][nt][3] += bias2[nt][1];
            ss[mt][0] = fmaf(acc[mt][nt][0], acc[mt][nt][0],
                        fmaf(acc[mt][nt][1], acc[mt][nt][1], ss[mt][0]));
            ss[mt][1] = fmaf(acc[mt][nt][2], acc[mt][nt][2],
                        fmaf(acc[mt][nt][3], acc[mt][nt][3], ss[mt][1]));
        }
#pragma unroll
    for (int m = 1; m <= 2; m <<= 1) {
#pragma unroll
        for (int mt = 0; mt < 2; mt++) {
            ss[mt][0] += __shfl_xor_sync(0xFFFFFFFFu, ss[mt][0], m);
            ss[mt][1] += __shfl_xor_sync(0xFFFFFFFFu, ss[mt][1], m);
        }
    }
    float* red  = (float*)smem;
    float* invp = red + 256;
    const int wcol = wid >> 1;
    __syncthreads();
    if ((lane & 3) == 0) {
#pragma unroll
        for (int mt = 0; mt < 2; mt++) {
            red[(wm + mt * 16 + r_in) * 4 + wcol]     = ss[mt][0];
            red[(wm + mt * 16 + r_in + 8) * 4 + wcol] = ss[mt][1];
        }
    }
    __syncthreads();
    if (tid < 64) {
        float s = red[tid * 4] + red[tid * 4 + 1] + red[tid * 4 + 2] + red[tid * 4 + 3];
        invp[tid] = 1.f / fmaxf(sqrtf(s), 1e-12f);
    }
    __syncthreads();
#pragma unroll
    for (int mt = 0; mt < 2; mt++) {
        const int rl = wm + mt * 16 + r_in;
        const float inv0 = invp[rl], inv1 = invp[rl + 8];
        const int r0 = bmg + rl;
#pragma unroll
        for (int nt = 0; nt < 4; nt++) {
            const int col = wn + nt * 8 + c_in;
            *(uint32_t*)(Zf + (size_t)r0 * Ntot + col) =
                packh2(acc[mt][nt][0] * inv0, acc[mt][nt][1] * inv0);
            *(uint32_t*)(Zf + (size_t)(r0 + 8) * Ntot + col) =
                packh2(acc[mt][nt][2] * inv1, acc[mt][nt][3] * inv1);
        }
    }
}

// ===========================================================================
// Final NT GEMM: C = Zx @ Zy^T, K=128, fp16. CTA = 128x256 strip (2 tiles),
// 512 threads, 16 warps (4x4), warp tile 32x32. A once, B double-buffered,
// 1 barrier/tile. 2 CTAs/SM. Grid 2048 (~6.9 waves, small tail).
// ===========================================================================
#define FSTR      272
#define F_A       0
#define F_B0      (128 * FSTR)
#define F_B1      (F_B0 + 128 * FSTR)
#define NTF_SMEM  (3 * 128 * FSTR)       // 104448 B

__global__ __launch_bounds__(512, 2) void gemm_nt_f16(
    const __half* __restrict__ ZA, const __half* __restrict__ ZB,
    float* __restrict__ C)
{
    extern __shared__ char smem[];
    const uint32_t sbase = smem_u32(smem);
    const int tid = threadIdx.x;
    const int bm = blockIdx.y << 7;
    const int bn = blockIdx.x << 8;          // 256-col strip (2 tiles)

    const int row = tid >> 2;                // 0..127
    const int q   = tid & 3;                 // 64 B per thread
    const uint32_t dof = (uint32_t)row * FSTR + (uint32_t)q * 64;

    // initial group: A + B0
    {
        const char* sa = (const char*)(ZA + (size_t)(bm + row) * LAT + q * 32);
        const char* sb = (const char*)(ZB + (size_t)(bn + row) * LAT + q * 32);
#pragma unroll
        for (int c = 0; c < 4; c++) {
            cpa16(sbase + F_A  + dof + c * 16, sa + c * 16);
            cpa16(sbase + F_B0 + dof + c * 16, sb + c * 16);
        }
    }
    CP_COMMIT();

    const int wid  = tid >> 5;
    const int lane = tid & 31;
    const int wm = (wid & 3) << 5;           // 0..96
    const int wn = (wid >> 2) << 5;          // 0..96
    const int lrow  = lane & 15;
    const int khalf = lane >> 4;
    const int r_in = lane >> 2;
    const int c_in = (lane & 3) << 1;

#pragma unroll
    for (int t = 0; t < 2; t++) {
        CP_WAIT0();
        __syncthreads();
        if (t + 1 < 2) {
            const int brow = bn + (t + 1) * 128 + row;
            const char* sb = (const char*)(ZB + (size_t)brow * LAT + q * 32);
#pragma unroll
            for (int c = 0; c < 4; c++)
                cpa16(sbase + F_B1 + dof + c * 16, sb + c * 16);
            CP_COMMIT();
        }

        const uint32_t bbase = sbase + ((t & 1) ? F_B1 : F_B0);

        float acc[2][4][4];
#pragma unroll
        for (int mt = 0; mt < 2; mt++)
#pragma unroll
            for (int nt = 0; nt < 4; nt++)
#pragma unroll
                for (int e = 0; e < 4; e++) acc[mt][nt][e] = 0.f;

#pragma unroll
        for (int ks = 0; ks < 8; ks++) {
            const uint32_t koff = (uint32_t)ks * 32 + (uint32_t)khalf * 16;
            uint32_t a[2][4];
#pragma unroll
            for (int mt = 0; mt < 2; mt++)
                ldmx4(a[mt], sbase + F_A + (uint32_t)(wm + mt * 16 + lrow) * FSTR + koff);
#pragma unroll
            for (int np = 0; np < 2; np++) {
                uint32_t b[4];
                ldmx4(b, bbase + (uint32_t)(wn + np * 16 + lrow) * FSTR + koff);
#pragma unroll
                for (int mt = 0; mt < 2; mt++) {
                    mma16816h(acc[mt][2*np+0], a[mt], b[0], b[2]);
                    mma16816h(acc[mt][2*np+1], a[mt], b[1], b[3]);
                }
            }
        }

        // per-tile epilogue
        const int r0 = bm + wm + r_in;
        const int c0 = bn + t * 128 + wn + c_in;
#pragma unroll
        for (int mt = 0; mt < 2; mt++) {
#pragma unroll
            for (int nt = 0; nt < 4; nt++) {
                float* p0 = C + (size_t)(r0 + mt * 16)     * NR + c0 + nt * 8;
                float* p1 = C + (size_t)(r0 + mt * 16 + 8) * NR + c0 + nt * 8;
                *(float2*)p0 = make_float2(acc[mt][nt][0], acc[mt][nt][1]);
                *(float2*)p1 = make_float2(acc[mt][nt][2], acc[mt][nt][3]);
            }
        }
    }
}

// ===========================================================================
extern "C" void kernel_launch(void* const* d_in, const int* in_sizes, int n_in,
                              void* d_out, int out_size)
{
    const float* x  = (const float*)d_in[0];
    const float* y  = (const float*)d_in[1];
    const float* W1 = (const float*)d_in[2];
    const float* b1 = (const float*)d_in[3];
    const float* W2 = (const float*)d_in[4];
    const float* b2 = (const float*)d_in[5];
    const float* W3 = (const float*)d_in[6];
    const float* b3 = (const float*)d_in[7];
    float* out = (float*)d_out;

    __half *H1, *H2, *Zf, *WT1, *WT2, *WT3;
    cudaGetSymbolAddress((void**)&H1,  g_H1);
    cudaGetSymbolAddress((void**)&H2,  g_H2);
    cudaGetSymbolAddress((void**)&Zf,  g_Zf);
    cudaGetSymbolAddress((void**)&WT1, g_WT1);
    cudaGetSymbolAddress((void**)&WT2, g_WT2);
    cudaGetSymbolAddress((void**)&WT3, g_WT3);

    cudaFuncSetAttribute(gemm_nt_f16, cudaFuncAttributeMaxDynamicSharedMemorySize, NTF_SMEM);
    cudaFuncSetAttribute(gemm_norm64, cudaFuncAttributeMaxDynamicSharedMemorySize, N3_SMEM);
    cudaFuncSetAttribute(gemm_enc<64,  true>,  cudaFuncAttributeMaxDynamicSharedMemorySize, ENC_SMEM);
    cudaFuncSetAttribute(gemm_enc<512, false>, cudaFuncAttributeMaxDynamicSharedMemorySize, ENC_SMEM);

    // launch 1, 2: weight prep
    prep_w13<<<(HID * DIM + LAT * HID + 255) / 256, 256>>>(W1, W3, WT1, WT3);
    prep_w2 <<<(HID * HID + 255) / 256, 256>>>(W2, WT2);

    // launch 3: layer 1 (fp32 x/y fused)
    dim3 g1(HID / 128, 2 * NR / 128);
    gemm_enc<64, true><<<g1, 512, ENC_SMEM>>>(x, y, WT1, b1, H1, HID);

    // launch 4 (profiled): layer 2
    dim3 g2(HID / 128, 2 * NR / 128);
    gemm_enc<512, false><<<g2, 512, ENC_SMEM>>>(H1, nullptr, WT2, b2, H2, HID);

    // launch 5: layer 3 + L2 norm (3 CTAs/SM)
    dim3 g3(1, 2 * NR / 64);
    gemm_norm64<<<g3, 256, N3_SMEM>>>(H2, WT3, b3, Zf);

    // launch 6: similarity (2-tile strips, grid 2048)
    dim3 g4(NR / 256, NR / 128);
    gemm_nt_f16<<<g4, 512, NTF_SMEM>>>(Zf, Zf + (size_t)NR * LAT, out);
}

// round 14
// speedup vs baseline: 1.1885x; 1.0175x over previous
#include <cuda_runtime.h>
#include <cuda_bf16.h>
#include <cuda_fp16.h>
#include <math.h>
#include <cstdint>

#define NR   8192
#define DIM  64
#define HID  512
#define LAT  128

// Scratch (device globals — allocation-free per harness rules)
__device__ __half g_H1[2 * NR * HID];    // 16 MB
__device__ __half g_H2[2 * NR * HID];    // 16 MB
__device__ __half g_Zf[2 * NR * LAT];    //  4 MB
__device__ __half g_WT1[HID * DIM];
__device__ __half g_WT2[HID * HID];
__device__ __half g_WT3[LAT * HID];

// ===========================================================================
// helpers
// ===========================================================================
__device__ __forceinline__ uint32_t smem_u32(const void* p) {
    uint32_t a;
    asm("{ .reg .u64 t; cvta.to.shared.u64 t, %1; cvt.u32.u64 %0, t; }"
        : "=r"(a) : "l"(p));
    return a;
}
__device__ __forceinline__ void ldmx4(uint32_t* r, uint32_t addr) {
    asm volatile("ldmatrix.sync.aligned.m8n8.x4.shared.b16 {%0,%1,%2,%3}, [%4];"
                 : "=r"(r[0]), "=r"(r[1]), "=r"(r[2]), "=r"(r[3]) : "r"(addr));
}
__device__ __forceinline__ void mma16816h(float* d, const uint32_t* a,
                                          uint32_t b0, uint32_t b1) {
    asm volatile(
        "mma.sync.aligned.m16n8k16.row.col.f32.f16.f16.f32 "
        "{%0,%1,%2,%3}, {%4,%5,%6,%7}, {%8,%9}, {%0,%1,%2,%3};"
        : "+f"(d[0]), "+f"(d[1]), "+f"(d[2]), "+f"(d[3])
        : "r"(a[0]), "r"(a[1]), "r"(a[2]), "r"(a[3]), "r"(b0), "r"(b1));
}
__device__ __forceinline__ void cpa16(uint32_t dst, const void* src) {
    asm volatile("cp.async.cg.shared.global [%0], [%1], 16;"
                 :: "r"(dst), "l"(src));
}
#define CP_COMMIT() asm volatile("cp.async.commit_group;")
#define CP_WAIT0()  asm volatile("cp.async.wait_group 0;" ::: "memory")

__device__ __forceinline__ uint32_t packh2(float a, float b) {
    uint32_t r;
    asm("cvt.rn.f16x2.f32 %0, %1, %2;" : "=r"(r) : "f"(b), "f"(a));
    return r;
}
// streaming (evict-first) fp32x2 store — keeps Z resident in L2
__device__ __forceinline__ void stcs2(float* p, float a, float b) {
    asm volatile("st.global.cs.v2.f32 [%0], {%1, %2};"
                 :: "l"(p), "f"(a), "f"(b) : "memory");
}

// ===========================================================================
// prep kernels
// ===========================================================================
__global__ void prep_w2(const float* __restrict__ W,
                        __half* __restrict__ WT) {
    int idx = blockIdx.x * blockDim.x + threadIdx.x;
    if (idx >= HID * HID) return;
    int n = idx / HID, k = idx - n * HID;
    WT[idx] = __float2half(W[(size_t)k * HID + n]);
}
__global__ void prep_w13(const float* __restrict__ W1s, const float* __restrict__ W3s,
                         __half* __restrict__ WT1d, __half* __restrict__ WT3d) {
    int idx = blockIdx.x * blockDim.x + threadIdx.x;
    if (idx < HID * DIM) {
        int n = idx / DIM, k = idx - n * DIM;
        WT1d[idx] = __float2half(W1s[(size_t)k * HID + n]);
    } else if (idx < HID * DIM + LAT * HID) {
        int j = idx - HID * DIM;
        int n = j / HID, k = j - n * HID;
        WT3d[j] = __float2half(W3s[(size_t)k * LAT + n]);
    }
}

// ===========================================================================
// Encoder mma GEMM (layers 1,2): 512 threads, 16 warps (4x4), warp tile
// 32x32, CTA 128x128, BK=64 double-buffered, 2 CTAs/SM. (round-12 validated)
// ===========================================================================
#define ESTR      144
#define ET        (128 * ESTR)
#define ENC_SMEM  (4 * ET)               // 73728

template<int K, bool A_FP32>
__global__ __launch_bounds__(512, 2) void gemm_enc(
    const void* __restrict__ Ax, const void* __restrict__ Ay,
    const __half* __restrict__ B,
    const float* __restrict__ bias,
    __half* __restrict__ Cf, int Ntot)
{
    constexpr int CH = K / 64;
    extern __shared__ char smem[];
    const uint32_t sbase = smem_u32(smem);
    const int tid = threadIdx.x;
    const int bmg = blockIdx.y << 7, bn = blockIdx.x << 7;
    const int wid = tid >> 5, lane = tid & 31;
    const int wm = (wid & 3) << 5, wn = (wid >> 2) << 5;
    const int lrow = lane & 15, khalf = lane >> 4;

    const float* Af32 = nullptr;
    const __half* Af16 = nullptr;
    int bm;
    if (A_FP32) {
        Af32 = (bmg < NR) ? (const float*)Ax : (const float*)Ay;
        bm = (bmg < NR) ? bmg : bmg - NR;
    } else {
        Af16 = (const __half*)Ax;
        bm = bmg;
    }

    float acc[2][4][4];
#pragma unroll
    for (int mt = 0; mt < 2; mt++)
#pragma unroll
        for (int nt = 0; nt < 4; nt++)
#pragma unroll
            for (int e = 0; e < 4; e++) acc[mt][nt][e] = 0.f;

    const int lr  = tid >> 2;           // 0..127
    const int ksg = (tid & 3) << 4;     // 0,16,32,48 elements

    auto load_chunk = [&](int c, int buf) {
        const uint32_t abase = sbase + (uint32_t)(buf * 2) * ET;
        const uint32_t bbase = abase + ET;
        const uint32_t ob = (uint32_t)lr * ESTR + (uint32_t)ksg * 2;
        if (A_FP32) {
            const float* ap = Af32 + (size_t)(bm + lr) * K + c * 64 + ksg;
#pragma unroll
            for (int q = 0; q < 2; q++) {
                float4 f0 = *(const float4*)(ap + q * 8);
                float4 f1 = *(const float4*)(ap + q * 8 + 4);
                uint4 v;
                v.x = packh2(f0.x, f0.y); v.y = packh2(f0.z, f0.w);
                v.z = packh2(f1.x, f1.y); v.w = packh2(f1.z, f1.w);
                *(uint4*)(smem + (abase - sbase) + ob + q * 16) = v;
            }
        } else {
            const char* ap = (const char*)(Af16 + (size_t)(bm + lr) * K + c * 64 + ksg);
            cpa16(abase + ob,      ap);
            cpa16(abase + ob + 16, ap + 16);
        }
        const char* bp = (const char*)(B + (size_t)(bn + lr) * K + c * 64 + ksg);
        cpa16(bbase + ob,      bp);
        cpa16(bbase + ob + 16, bp + 16);
    };

    load_chunk(0, 0);
    CP_COMMIT();

    for (int c = 0; c < CH; c++) {
        CP_WAIT0();
        __syncthreads();
        if (c + 1 < CH) {
            load_chunk(c + 1, (c + 1) & 1);
            CP_COMMIT();
        }

        const uint32_t abase = sbase + (uint32_t)((c & 1) * 2) * ET;
        const uint32_t bbase = abase + ET;
#pragma unroll
        for (int ks = 0; ks < 4; ks++) {
            const uint32_t koff = (uint32_t)ks * 32 + (uint32_t)khalf * 16;
            uint32_t a[2][4];
#pragma unroll
            for (int mt = 0; mt < 2; mt++)
                ldmx4(a[mt], abase + (uint32_t)(wm + mt * 16 + lrow) * ESTR + koff);
#pragma unroll
            for (int np = 0; np < 2; np++) {
                uint32_t t[4];
                ldmx4(t, bbase + (uint32_t)(wn + np * 16 + lrow) * ESTR + koff);
#pragma unroll
                for (int mt = 0; mt < 2; mt++) {
                    mma16816h(acc[mt][2*np+0], a[mt], t[0], t[2]);
                    mma16816h(acc[mt][2*np+1], a[mt], t[1], t[3]);
                }
            }
        }
    }

    const int r_in = lane >> 2;
    const int c_in = (lane & 3) << 1;

#pragma unroll
    for (int mt = 0; mt < 2; mt++) {
        const int r0 = bmg + wm + mt * 16 + r_in;
#pragma unroll
        for (int nt = 0; nt < 4; nt++) {
            const int col = bn + wn + nt * 8 + c_in;
            const float b0 = bias[col], b1 = bias[col + 1];
            float o0 = fmaxf(acc[mt][nt][0] + b0, 0.f);
            float o1 = fmaxf(acc[mt][nt][1] + b1, 0.f);
            float o2 = fmaxf(acc[mt][nt][2] + b0, 0.f);
            float o3 = fmaxf(acc[mt][nt][3] + b1, 0.f);
            *(uint32_t*)(Cf + (size_t)r0 * Ntot + col)       = packh2(o0, o1);
            *(uint32_t*)(Cf + (size_t)(r0 + 8) * Ntot + col) = packh2(o2, o3);
        }
    }
}

// ===========================================================================
// Layer 3 + L2 norm: CTA 64x128, K=512 (BK=64, double-buffered), 256 thr,
// 8 warps (2 M x 4 N), grid 512, 3 CTAs/SM. (round-13 validated)
// ===========================================================================
#define N3_A      (64 * ESTR)
#define N3_B      (128 * ESTR)
#define N3_AB     (N3_A + N3_B)
#define N3_SMEM   (2 * N3_AB)

__global__ __launch_bounds__(256, 3) void gemm_norm64(
    const __half* __restrict__ A, const __half* __restrict__ B,
    const float* __restrict__ bias, __half* __restrict__ Zf)
{
    constexpr int K = HID, CH = K / 64, Ntot = LAT;
    extern __shared__ char smem[];
    const uint32_t sbase = smem_u32(smem);
    const int tid = threadIdx.x;
    const int bmg = blockIdx.y << 6;
    const int wid = tid >> 5, lane = tid & 31;
    const int wm = (wid & 1) << 5, wn = (wid >> 1) << 5;
    const int lrow = lane & 15, khalf = lane >> 4;

    float acc[2][4][4];
#pragma unroll
    for (int mt = 0; mt < 2; mt++)
#pragma unroll
        for (int nt = 0; nt < 4; nt++)
#pragma unroll
            for (int e = 0; e < 4; e++) acc[mt][nt][e] = 0.f;

    const int lra = tid >> 2, ka = (tid & 3) << 4;
    const int lrb = tid >> 1, kb = (tid & 1) << 5;

    auto load_chunk = [&](int c, int buf) {
        const uint32_t abase = sbase + (uint32_t)buf * N3_AB;
        const uint32_t bbase = abase + N3_A;
        const uint32_t oa = (uint32_t)lra * ESTR + (uint32_t)ka * 2;
        const char* ap = (const char*)(A + (size_t)(bmg + lra) * K + c * 64 + ka);
        cpa16(abase + oa,      ap);
        cpa16(abase + oa + 16, ap + 16);
        const uint32_t obp = (uint32_t)lrb * ESTR + (uint32_t)kb * 2;
        const char* bp = (const char*)(B + (size_t)lrb * K + c * 64 + kb);
#pragma unroll
        for (int q = 0; q < 4; q++)
            cpa16(bbase + obp + q * 16, bp + q * 16);
    };

    load_chunk(0, 0);
    CP_COMMIT();

    for (int c = 0; c < CH; c++) {
        CP_WAIT0();
        __syncthreads();
        if (c + 1 < CH) {
            load_chunk(c + 1, (c + 1) & 1);
            CP_COMMIT();
        }

        const uint32_t abase = sbase + (uint32_t)(c & 1) * N3_AB;
        const uint32_t bbase = abase + N3_A;
#pragma unroll
        for (int ks = 0; ks < 4; ks++) {
            const uint32_t koff = (uint32_t)ks * 32 + (uint32_t)khalf * 16;
            uint32_t a[2][4];
#pragma unroll
            for (int mt = 0; mt < 2; mt++)
                ldmx4(a[mt], abase + (uint32_t)(wm + mt * 16 + lrow) * ESTR + koff);
#pragma unroll
            for (int np = 0; np < 2; np++) {
                uint32_t t[4];
                ldmx4(t, bbase + (uint32_t)(wn + np * 16 + lrow) * ESTR + koff);
#pragma unroll
                for (int mt = 0; mt < 2; mt++) {
                    mma16816h(acc[mt][2*np+0], a[mt], t[0], t[2]);
                    mma16816h(acc[mt][2*np+1], a[mt], t[1], t[3]);
                }
            }
        }
    }

    const int r_in = lane >> 2;
    const int c_in = (lane & 3) << 1;

    float bias2[4][2];
#pragma unroll
    for (int nt = 0; nt < 4; nt++) {
        bias2[nt][0] = bias[wn + nt * 8 + c_in];
        bias2[nt][1] = bias[wn + nt * 8 + c_in + 1];
    }

    float ss[2][2] = {{0.f, 0.f}, {0.f, 0.f}};
#pragma unroll
    for (int mt = 0; mt < 2; mt++)
#pragma unroll
        for (int nt = 0; nt < 4; nt++) {
            acc[mt][nt][0] += bias2[nt][0];
            acc[mt][nt][1] += bias2[nt][1];
            acc[mt][nt][2] += bias2[nt][0];
            acc[mt][nt][3] += bias2[nt][1];
            ss[mt][0] = fmaf(acc[mt][nt][0], acc[mt][nt][0],
                        fmaf(acc[mt][nt][1], acc[mt][nt][1], ss[mt][0]));
            ss[mt][1] = fmaf(acc[mt][nt][2], acc[mt][nt][2],
                        fmaf(acc[mt][nt][3], acc[mt][nt][3], ss[mt][1]));
        }
#pragma unroll
    for (int m = 1; m <= 2; m <<= 1) {
#pragma unroll
        for (int mt = 0; mt < 2; mt++) {
            ss[mt][0] += __shfl_xor_sync(0xFFFFFFFFu, ss[mt][0], m);
            ss[mt][1] += __shfl_xor_sync(0xFFFFFFFFu, ss[mt][1], m);
        }
    }
    float* red  = (float*)smem;
    float* invp = red + 256;
    const int wcol = wid >> 1;
    __syncthreads();
    if ((lane & 3) == 0) {
#pragma unroll
        for (int mt = 0; mt < 2; mt++) {
            red[(wm + mt * 16 + r_in) * 4 + wcol]     = ss[mt][0];
            red[(wm + mt * 16 + r_in + 8) * 4 + wcol] = ss[mt][1];
        }
    }
    __syncthreads();
    if (tid < 64) {
        float s = red[tid * 4] + red[tid * 4 + 1] + red[tid * 4 + 2] + red[tid * 4 + 3];
        invp[tid] = 1.f / fmaxf(sqrtf(s), 1e-12f);
    }
    __syncthreads();
#pragma unroll
    for (int mt = 0; mt < 2; mt++) {
        const int rl = wm + mt * 16 + r_in;
        const float inv0 = invp[rl], inv1 = invp[rl + 8];
        const int r0 = bmg + rl;
#pragma unroll
        for (int nt = 0; nt < 4; nt++) {
            const int col = wn + nt * 8 + c_in;
            *(uint32_t*)(Zf + (size_t)r0 * Ntot + col) =
                packh2(acc[mt][nt][0] * inv0, acc[mt][nt][1] * inv0);
            *(uint32_t*)(Zf + (size_t)(r0 + 8) * Ntot + col) =
                packh2(acc[mt][nt][2] * inv1, acc[mt][nt][3] * inv1);
        }
    }
}

// ===========================================================================
// Final NT GEMM: C = Zx @ Zy^T, K=128, fp16. CTA = 128x256 strip (2 tiles),
// 512 threads, 16 warps (4x4), warp tile 32x32. A once, B double-buffered,
// 1 barrier/tile. 2 CTAs/SM. Grid 2048. Streaming (.cs) C stores so Z stays
// L2-resident.
// ===========================================================================
#define FSTR      272
#define F_A       0
#define F_B0      (128 * FSTR)
#define F_B1      (F_B0 + 128 * FSTR)
#define NTF_SMEM  (3 * 128 * FSTR)       // 104448 B

__global__ __launch_bounds__(512, 2) void gemm_nt_f16(
    const __half* __restrict__ ZA, const __half* __restrict__ ZB,
    float* __restrict__ C)
{
    extern __shared__ char smem[];
    const uint32_t sbase = smem_u32(smem);
    const int tid = threadIdx.x;
    const int bm = blockIdx.y << 7;
    const int bn = blockIdx.x << 8;          // 256-col strip (2 tiles)

    const int row = tid >> 2;                // 0..127
    const int q   = tid & 3;                 // 64 B per thread
    const uint32_t dof = (uint32_t)row * FSTR + (uint32_t)q * 64;

    // initial group: A + B0
    {
        const char* sa = (const char*)(ZA + (size_t)(bm + row) * LAT + q * 32);
        const char* sb = (const char*)(ZB + (size_t)(bn + row) * LAT + q * 32);
#pragma unroll
        for (int c = 0; c < 4; c++) {
            cpa16(sbase + F_A  + dof + c * 16, sa + c * 16);
            cpa16(sbase + F_B0 + dof + c * 16, sb + c * 16);
        }
    }
    CP_COMMIT();

    const int wid  = tid >> 5;
    const int lane = tid & 31;
    const int wm = (wid & 3) << 5;           // 0..96
    const int wn = (wid >> 2) << 5;          // 0..96
    const int lrow  = lane & 15;
    const int khalf = lane >> 4;
    const int r_in = lane >> 2;
    const int c_in = (lane & 3) << 1;

#pragma unroll
    for (int t = 0; t < 2; t++) {
        CP_WAIT0();
        __syncthreads();
        if (t + 1 < 2) {
            const int brow = bn + (t + 1) * 128 + row;
            const char* sb = (const char*)(ZB + (size_t)brow * LAT + q * 32);
#pragma unroll
            for (int c = 0; c < 4; c++)
                cpa16(sbase + F_B1 + dof + c * 16, sb + c * 16);
            CP_COMMIT();
        }

        const uint32_t bbase = sbase + ((t & 1) ? F_B1 : F_B0);

        float acc[2][4][4];
#pragma unroll
        for (int mt = 0; mt < 2; mt++)
#pragma unroll
            for (int nt = 0; nt < 4; nt++)
#pragma unroll
                for (int e = 0; e < 4; e++) acc[mt][nt][e] = 0.f;

#pragma unroll
        for (int ks = 0; ks < 8; ks++) {
            const uint32_t koff = (uint32_t)ks * 32 + (uint32_t)khalf * 16;
            uint32_t a[2][4];
#pragma unroll
            for (int mt = 0; mt < 2; mt++)
                ldmx4(a[mt], sbase + F_A + (uint32_t)(wm + mt * 16 + lrow) * FSTR + koff);
#pragma unroll
            for (int np = 0; np < 2; np++) {
                uint32_t b[4];
                ldmx4(b, bbase + (uint32_t)(wn + np * 16 + lrow) * FSTR + koff);
#pragma unroll
                for (int mt = 0; mt < 2; mt++) {
                    mma16816h(acc[mt][2*np+0], a[mt], b[0], b[2]);
                    mma16816h(acc[mt][2*np+1], a[mt], b[1], b[3]);
                }
            }
        }

        // per-tile epilogue — streaming stores (evict-first)
        const int r0 = bm + wm + r_in;
        const int c0 = bn + t * 128 + wn + c_in;
#pragma unroll
        for (int mt = 0; mt < 2; mt++) {
#pragma unroll
            for (int nt = 0; nt < 4; nt++) {
                float* p0 = C + (size_t)(r0 + mt * 16)     * NR + c0 + nt * 8;
                float* p1 = C + (size_t)(r0 + mt * 16 + 8) * NR + c0 + nt * 8;
                stcs2(p0, acc[mt][nt][0], acc[mt][nt][1]);
                stcs2(p1, acc[mt][nt][2], acc[mt][nt][3]);
            }
        }
    }
}

// ===========================================================================
extern "C" void kernel_launch(void* const* d_in, const int* in_sizes, int n_in,
                              void* d_out, int out_size)
{
    const float* x  = (const float*)d_in[0];
    const float* y  = (const float*)d_in[1];
    const float* W1 = (const float*)d_in[2];
    const float* b1 = (const float*)d_in[3];
    const float* W2 = (const float*)d_in[4];
    const float* b2 = (const float*)d_in[5];
    const float* W3 = (const float*)d_in[6];
    const float* b3 = (const float*)d_in[7];
    float* out = (float*)d_out;

    __half *H1, *H2, *Zf, *WT1, *WT2, *WT3;
    cudaGetSymbolAddress((void**)&H1,  g_H1);
    cudaGetSymbolAddress((void**)&H2,  g_H2);
    cudaGetSymbolAddress((void**)&Zf,  g_Zf);
    cudaGetSymbolAddress((void**)&WT1, g_WT1);
    cudaGetSymbolAddress((void**)&WT2, g_WT2);
    cudaGetSymbolAddress((void**)&WT3, g_WT3);

    cudaFuncSetAttribute(gemm_nt_f16, cudaFuncAttributeMaxDynamicSharedMemorySize, NTF_SMEM);
    cudaFuncSetAttribute(gemm_norm64, cudaFuncAttributeMaxDynamicSharedMemorySize, N3_SMEM);
    cudaFuncSetAttribute(gemm_enc<64,  true>,  cudaFuncAttributeMaxDynamicSharedMemorySize, ENC_SMEM);
    cudaFuncSetAttribute(gemm_enc<512, false>, cudaFuncAttributeMaxDynamicSharedMemorySize, ENC_SMEM);

    // launch 1, 2: weight prep
    prep_w13<<<(HID * DIM + LAT * HID + 255) / 256, 256>>>(W1, W3, WT1, WT3);
    prep_w2 <<<(HID * HID + 255) / 256, 256>>>(W2, WT2);

    // launch 3: layer 1 (fp32 x/y fused)
    dim3 g1(HID / 128, 2 * NR / 128);
    gemm_enc<64, true><<<g1, 512, ENC_SMEM>>>(x, y, WT1, b1, H1, HID);

    // launch 4 (profiled): layer 2
    dim3 g2(HID / 128, 2 * NR / 128);
    gemm_enc<512, false><<<g2, 512, ENC_SMEM>>>(H1, nullptr, WT2, b2, H2, HID);

    // launch 5: layer 3 + L2 norm (3 CTAs/SM)
    dim3 g3(1, 2 * NR / 64);
    gemm_norm64<<<g3, 256, N3_SMEM>>>(H2, WT3, b3, Zf);

    // launch 6: similarity (2-tile strips, streaming stores)
    dim3 g4(NR / 256, NR / 128);
    gemm_nt_f16<<<g4, 512, NTF_SMEM>>>(Zf, Zf + (size_t)NR * LAT, out);
}

// round 15
// speedup vs baseline: 1.1915x; 1.0025x over previous
#include <cuda_runtime.h>
#include <cuda_bf16.h>
#include <cuda_fp16.h>
#include <math.h>
#include <cstdint>

#define NR   8192
#define DIM  64
#define HID  512
#define LAT  128

// Scratch (device globals — allocation-free per harness rules)
__device__ __half g_H1[2 * NR * HID];    // 16 MB
__device__ __half g_H2[2 * NR * HID];    // 16 MB
__device__ __half g_Zf[2 * NR * LAT];    //  4 MB
__device__ __half g_WT1[HID * DIM];
__device__ __half g_WT2[HID * HID];
__device__ __half g_WT3[LAT * HID];

// ===========================================================================
// helpers
// ===========================================================================
__device__ __forceinline__ uint32_t smem_u32(const void* p) {
    uint32_t a;
    asm("{ .reg .u64 t; cvta.to.shared.u64 t, %1; cvt.u32.u64 %0, t; }"
        : "=r"(a) : "l"(p));
    return a;
}
__device__ __forceinline__ void ldmx4(uint32_t* r, uint32_t addr) {
    asm volatile("ldmatrix.sync.aligned.m8n8.x4.shared.b16 {%0,%1,%2,%3}, [%4];"
                 : "=r"(r[0]), "=r"(r[1]), "=r"(r[2]), "=r"(r[3]) : "r"(addr));
}
__device__ __forceinline__ void mma16816h(float* d, const uint32_t* a,
                                          uint32_t b0, uint32_t b1) {
    asm volatile(
        "mma.sync.aligned.m16n8k16.row.col.f32.f16.f16.f32 "
        "{%0,%1,%2,%3}, {%4,%5,%6,%7}, {%8,%9}, {%0,%1,%2,%3};"
        : "+f"(d[0]), "+f"(d[1]), "+f"(d[2]), "+f"(d[3])
        : "r"(a[0]), "r"(a[1]), "r"(a[2]), "r"(a[3]), "r"(b0), "r"(b1));
}
__device__ __forceinline__ void cpa16(uint32_t dst, const void* src) {
    asm volatile("cp.async.cg.shared.global [%0], [%1], 16;"
                 :: "r"(dst), "l"(src));
}
#define CP_COMMIT() asm volatile("cp.async.commit_group;")
#define CP_WAIT0()  asm volatile("cp.async.wait_group 0;" ::: "memory")

__device__ __forceinline__ uint32_t packh2(float a, float b) {
    uint32_t r;
    asm("cvt.rn.f16x2.f32 %0, %1, %2;" : "=r"(r) : "f"(b), "f"(a));
    return r;
}
__device__ __forceinline__ void stcs2(float* p, float a, float b) {
    asm volatile("st.global.cs.v2.f32 [%0], {%1, %2};"
                 :: "l"(p), "f"(a), "f"(b) : "memory");
}
// XOR-swizzled offset for 256B rows (128 fp16), unit = 16B column index
__device__ __forceinline__ uint32_t swoff(int r, int u) {
    return (uint32_t)r * 256u + (uint32_t)((u ^ (r & 7)) << 4);
}

// ===========================================================================
// prep kernels
// ===========================================================================
__global__ void prep_w2(const float* __restrict__ W,
                        __half* __restrict__ WT) {
    int idx = blockIdx.x * blockDim.x + threadIdx.x;
    if (idx >= HID * HID) return;
    int n = idx / HID, k = idx - n * HID;
    WT[idx] = __float2half(W[(size_t)k * HID + n]);
}
__global__ void prep_w13(const float* __restrict__ W1s, const float* __restrict__ W3s,
                         __half* __restrict__ WT1d, __half* __restrict__ WT3d) {
    int idx = blockIdx.x * blockDim.x + threadIdx.x;
    if (idx < HID * DIM) {
        int n = idx / DIM, k = idx - n * DIM;
        WT1d[idx] = __float2half(W1s[(size_t)k * HID + n]);
    } else if (idx < HID * DIM + LAT * HID) {
        int j = idx - HID * DIM;
        int n = j / HID, k = j - n * HID;
        WT3d[j] = __float2half(W3s[(size_t)k * LAT + n]);
    }
}

// ===========================================================================
// Encoder mma GEMM (layers 1,2): 512 threads, 16 warps (4x4), warp tile
// 32x32, CTA 128x128, BK=64 double-buffered, 2 CTAs/SM. (round-12 validated)
// ===========================================================================
#define ESTR      144
#define ET        (128 * ESTR)
#define ENC_SMEM  (4 * ET)               // 73728

template<int K, bool A_FP32>
__global__ __launch_bounds__(512, 2) void gemm_enc(
    const void* __restrict__ Ax, const void* __restrict__ Ay,
    const __half* __restrict__ B,
    const float* __restrict__ bias,
    __half* __restrict__ Cf, int Ntot)
{
    constexpr int CH = K / 64;
    extern __shared__ char smem[];
    const uint32_t sbase = smem_u32(smem);
    const int tid = threadIdx.x;
    const int bmg = blockIdx.y << 7, bn = blockIdx.x << 7;
    const int wid = tid >> 5, lane = tid & 31;
    const int wm = (wid & 3) << 5, wn = (wid >> 2) << 5;
    const int lrow = lane & 15, khalf = lane >> 4;

    const float* Af32 = nullptr;
    const __half* Af16 = nullptr;
    int bm;
    if (A_FP32) {
        Af32 = (bmg < NR) ? (const float*)Ax : (const float*)Ay;
        bm = (bmg < NR) ? bmg : bmg - NR;
    } else {
        Af16 = (const __half*)Ax;
        bm = bmg;
    }

    float acc[2][4][4];
#pragma unroll
    for (int mt = 0; mt < 2; mt++)
#pragma unroll
        for (int nt = 0; nt < 4; nt++)
#pragma unroll
            for (int e = 0; e < 4; e++) acc[mt][nt][e] = 0.f;

    const int lr  = tid >> 2;           // 0..127
    const int ksg = (tid & 3) << 4;     // 0,16,32,48 elements

    auto load_chunk = [&](int c, int buf) {
        const uint32_t abase = sbase + (uint32_t)(buf * 2) * ET;
        const uint32_t bbase = abase + ET;
        const uint32_t ob = (uint32_t)lr * ESTR + (uint32_t)ksg * 2;
        if (A_FP32) {
            const float* ap = Af32 + (size_t)(bm + lr) * K + c * 64 + ksg;
#pragma unroll
            for (int q = 0; q < 2; q++) {
                float4 f0 = *(const float4*)(ap + q * 8);
                float4 f1 = *(const float4*)(ap + q * 8 + 4);
                uint4 v;
                v.x = packh2(f0.x, f0.y); v.y = packh2(f0.z, f0.w);
                v.z = packh2(f1.x, f1.y); v.w = packh2(f1.z, f1.w);
                *(uint4*)(smem + (abase - sbase) + ob + q * 16) = v;
            }
        } else {
            const char* ap = (const char*)(Af16 + (size_t)(bm + lr) * K + c * 64 + ksg);
            cpa16(abase + ob,      ap);
            cpa16(abase + ob + 16, ap + 16);
        }
        const char* bp = (const char*)(B + (size_t)(bn + lr) * K + c * 64 + ksg);
        cpa16(bbase + ob,      bp);
        cpa16(bbase + ob + 16, bp + 16);
    };

    load_chunk(0, 0);
    CP_COMMIT();

    for (int c = 0; c < CH; c++) {
        CP_WAIT0();
        __syncthreads();
        if (c + 1 < CH) {
            load_chunk(c + 1, (c + 1) & 1);
            CP_COMMIT();
        }

        const uint32_t abase = sbase + (uint32_t)((c & 1) * 2) * ET;
        const uint32_t bbase = abase + ET;
#pragma unroll
        for (int ks = 0; ks < 4; ks++) {
            const uint32_t koff = (uint32_t)ks * 32 + (uint32_t)khalf * 16;
            uint32_t a[2][4];
#pragma unroll
            for (int mt = 0; mt < 2; mt++)
                ldmx4(a[mt], abase + (uint32_t)(wm + mt * 16 + lrow) * ESTR + koff);
#pragma unroll
            for (int np = 0; np < 2; np++) {
                uint32_t t[4];
                ldmx4(t, bbase + (uint32_t)(wn + np * 16 + lrow) * ESTR + koff);
#pragma unroll
                for (int mt = 0; mt < 2; mt++) {
                    mma16816h(acc[mt][2*np+0], a[mt], t[0], t[2]);
                    mma16816h(acc[mt][2*np+1], a[mt], t[1], t[3]);
                }
            }
        }
    }

    const int r_in = lane >> 2;
    const int c_in = (lane & 3) << 1;

#pragma unroll
    for (int mt = 0; mt < 2; mt++) {
        const int r0 = bmg + wm + mt * 16 + r_in;
#pragma unroll
        for (int nt = 0; nt < 4; nt++) {
            const int col = bn + wn + nt * 8 + c_in;
            const float b0 = bias[col], b1 = bias[col + 1];
            float o0 = fmaxf(acc[mt][nt][0] + b0, 0.f);
            float o1 = fmaxf(acc[mt][nt][1] + b1, 0.f);
            float o2 = fmaxf(acc[mt][nt][2] + b0, 0.f);
            float o3 = fmaxf(acc[mt][nt][3] + b1, 0.f);
            *(uint32_t*)(Cf + (size_t)r0 * Ntot + col)       = packh2(o0, o1);
            *(uint32_t*)(Cf + (size_t)(r0 + 8) * Ntot + col) = packh2(o2, o3);
        }
    }
}

// ===========================================================================
// Layer 3 + L2 norm: CTA 64x128, K=512 (BK=64, double-buffered), 256 thr,
// 8 warps (2 M x 4 N), grid 512, 3 CTAs/SM. (round-13 validated)
// ===========================================================================
#define N3_A      (64 * ESTR)
#define N3_B      (128 * ESTR)
#define N3_AB     (N3_A + N3_B)
#define N3_SMEM   (2 * N3_AB)

__global__ __launch_bounds__(256, 3) void gemm_norm64(
    const __half* __restrict__ A, const __half* __restrict__ B,
    const float* __restrict__ bias, __half* __restrict__ Zf)
{
    constexpr int K = HID, CH = K / 64, Ntot = LAT;
    extern __shared__ char smem[];
    const uint32_t sbase = smem_u32(smem);
    const int tid = threadIdx.x;
    const int bmg = blockIdx.y << 6;
    const int wid = tid >> 5, lane = tid & 31;
    const int wm = (wid & 1) << 5, wn = (wid >> 1) << 5;
    const int lrow = lane & 15, khalf = lane >> 4;

    float acc[2][4][4];
#pragma unroll
    for (int mt = 0; mt < 2; mt++)
#pragma unroll
        for (int nt = 0; nt < 4; nt++)
#pragma unroll
            for (int e = 0; e < 4; e++) acc[mt][nt][e] = 0.f;

    const int lra = tid >> 2, ka = (tid & 3) << 4;
    const int lrb = tid >> 1, kb = (tid & 1) << 5;

    auto load_chunk = [&](int c, int buf) {
        const uint32_t abase = sbase + (uint32_t)buf * N3_AB;
        const uint32_t bbase = abase + N3_A;
        const uint32_t oa = (uint32_t)lra * ESTR + (uint32_t)ka * 2;
        const char* ap = (const char*)(A + (size_t)(bmg + lra) * K + c * 64 + ka);
        cpa16(abase + oa,      ap);
        cpa16(abase + oa + 16, ap + 16);
        const uint32_t obp = (uint32_t)lrb * ESTR + (uint32_t)kb * 2;
        const char* bp = (const char*)(B + (size_t)lrb * K + c * 64 + kb);
#pragma unroll
        for (int q = 0; q < 4; q++)
            cpa16(bbase + obp + q * 16, bp + q * 16);
    };

    load_chunk(0, 0);
    CP_COMMIT();

    for (int c = 0; c < CH; c++) {
        CP_WAIT0();
        __syncthreads();
        if (c + 1 < CH) {
            load_chunk(c + 1, (c + 1) & 1);
            CP_COMMIT();
        }

        const uint32_t abase = sbase + (uint32_t)(c & 1) * N3_AB;
        const uint32_t bbase = abase + N3_A;
#pragma unroll
        for (int ks = 0; ks < 4; ks++) {
            const uint32_t koff = (uint32_t)ks * 32 + (uint32_t)khalf * 16;
            uint32_t a[2][4];
#pragma unroll
            for (int mt = 0; mt < 2; mt++)
                ldmx4(a[mt], abase + (uint32_t)(wm + mt * 16 + lrow) * ESTR + koff);
#pragma unroll
            for (int np = 0; np < 2; np++) {
                uint32_t t[4];
                ldmx4(t, bbase + (uint32_t)(wn + np * 16 + lrow) * ESTR + koff);
#pragma unroll
                for (int mt = 0; mt < 2; mt++) {
                    mma16816h(acc[mt][2*np+0], a[mt], t[0], t[2]);
                    mma16816h(acc[mt][2*np+1], a[mt], t[1], t[3]);
                }
            }
        }
    }

    const int r_in = lane >> 2;
    const int c_in = (lane & 3) << 1;

    float bias2[4][2];
#pragma unroll
    for (int nt = 0; nt < 4; nt++) {
        bias2[nt][0] = bias[wn + nt * 8 + c_in];
        bias2[nt][1] = bias[wn + nt * 8 + c_in + 1];
    }

    float ss[2][2] = {{0.f, 0.f}, {0.f, 0.f}};
#pragma unroll
    for (int mt = 0; mt < 2; mt++)
#pragma unroll
        for (int nt = 0; nt < 4; nt++) {
            acc[mt][nt][0] += bias2[nt][0];
            acc[mt][nt][1] += bias2[nt][1];
            acc[mt][nt][2] += bias2[nt][0];
            acc[mt][nt][3] += bias2[nt][1];
            ss[mt][0] = fmaf(acc[mt][nt][0], acc[mt][nt][0],
                        fmaf(acc[mt][nt][1], acc[mt][nt][1], ss[mt][0]));
            ss[mt][1] = fmaf(acc[mt][nt][2], acc[mt][nt][2],
                        fmaf(acc[mt][nt][3], acc[mt][nt][3], ss[mt][1]));
        }
#pragma unroll
    for (int m = 1; m <= 2; m <<= 1) {
#pragma unroll
        for (int mt = 0; mt < 2; mt++) {
            ss[mt][0] += __shfl_xor_sync(0xFFFFFFFFu, ss[mt][0], m);
            ss[mt][1] += __shfl_xor_sync(0xFFFFFFFFu, ss[mt][1], m);
        }
    }
    float* red  = (float*)smem;
    float* invp = red + 256;
    const int wcol = wid >> 1;
    __syncthreads();
    if ((lane & 3) == 0) {
#pragma unroll
        for (int mt = 0; mt < 2; mt++) {
            red[(wm + mt * 16 + r_in) * 4 + wcol]     = ss[mt][0];
            red[(wm + mt * 16 + r_in + 8) * 4 + wcol] = ss[mt][1];
        }
    }
    __syncthreads();
    if (tid < 64) {
        float s = red[tid * 4] + red[tid * 4 + 1] + red[tid * 4 + 2] + red[tid * 4 + 3];
        invp[tid] = 1.f / fmaxf(sqrtf(s), 1e-12f);
    }
    __syncthreads();
#pragma unroll
    for (int mt = 0; mt < 2; mt++) {
        const int rl = wm + mt * 16 + r_in;
        const float inv0 = invp[rl], inv1 = invp[rl + 8];
        const int r0 = bmg + rl;
#pragma unroll
        for (int nt = 0; nt < 4; nt++) {
            const int col = wn + nt * 8 + c_in;
            *(uint32_t*)(Zf + (size_t)r0 * Ntot + col) =
                packh2(acc[mt][nt][0] * inv0, acc[mt][nt][1] * inv0);
            *(uint32_t*)(Zf + (size_t)(r0 + 8) * Ntot + col) =
                packh2(acc[mt][nt][2] * inv1, acc[mt][nt][3] * inv1);
        }
    }
}

// ===========================================================================
// Persistent NT GEMM: C = Zx @ Zy^T, K=128, fp16. 296 CTAs (2/SM, 1 wave),
// each processes ~14 consecutive 128x128 tiles (raster over 64x64 tile grid).
// XOR-swizzled smem (no pad): A buf + 2 B bufs = 96 KB. B prefetched across
// tiles; A reloaded only at bm transitions. 16 warps (4x4), warp tile 32x32.
// ===========================================================================
#define PT_TILES  4096                   // 64 x 64 tiles
#define PT_CTAS   296
#define TB        32768                  // one 128x128 fp16 tile
#define PT_SMEM   (3 * TB)               // 98304

__global__ __launch_bounds__(512, 2) void gemm_nt_persist(
    const __half* __restrict__ ZA, const __half* __restrict__ ZB,
    float* __restrict__ C)
{
    extern __shared__ char smem[];
    const uint32_t sbase = smem_u32(smem);
    const int tid = threadIdx.x;
    const int p = blockIdx.x;
    const int s = (p * PT_TILES) / PT_CTAS;
    const int e = ((p + 1) * PT_TILES) / PT_CTAS;

    const int row = tid >> 2;            // 0..127
    const int q   = tid & 3;             // 64 B per thread

    const int wid  = tid >> 5;
    const int lane = tid & 31;
    const int wm = (wid & 3) << 5;
    const int wn = (wid >> 2) << 5;
    const int lrow  = lane & 15;
    const int khalf = lane >> 4;
    const int r_in = lane >> 2;
    const int c_in = (lane & 3) << 1;

    // initial loads: A(bm of first tile) + B(first tile) -> buf 0
    int bmCur = s >> 6;
    {
        const char* sa = (const char*)(ZA + ((size_t)(bmCur << 7) + row) * LAT) + q * 64;
        const char* sb = (const char*)(ZB + ((size_t)((s & 63) << 7) + row) * LAT) + q * 64;
#pragma unroll
        for (int j = 0; j < 4; j++) {
            cpa16(sbase + swoff(row, q * 4 + j), sa + j * 16);
            cpa16(sbase + TB + swoff(row, q * 4 + j), sb + j * 16);
        }
    }
    CP_COMMIT();

    for (int i = s; i < e; i++) {
        CP_WAIT0();
        __syncthreads();                 // tile i data visible; buffers free

        const int bm = i >> 6, bn = i & 63;
        const int buf = (i - s) & 1;

        // prefetch next B tile into the other buffer
        if (i + 1 < e) {
            const int bn2 = (i + 1) & 63;
            const char* sb = (const char*)(ZB + ((size_t)(bn2 << 7) + row) * LAT) + q * 64;
            const uint32_t bbuf = sbase + TB + (uint32_t)(buf ^ 1) * TB;
#pragma unroll
            for (int j = 0; j < 4; j++)
                cpa16(bbuf + swoff(row, q * 4 + j), sb + j * 16);
            CP_COMMIT();
        }
        // rare: bm transition -> reload A (exposed once or twice per CTA)
        if (bm != bmCur) {
            const char* sa = (const char*)(ZA + ((size_t)(bm << 7) + row) * LAT) + q * 64;
#pragma unroll
            for (int j = 0; j < 4; j++)
                cpa16(sbase + swoff(row, q * 4 + j), sa + j * 16);
            CP_COMMIT();
            CP_WAIT0();                  // drains A (and the B prefetch; ok)
            __syncthreads();
            bmCur = bm;
        }

        const uint32_t bbase = sbase + TB + (uint32_t)buf * TB;

        float acc[2][4][4];
#pragma unroll
        for (int mt = 0; mt < 2; mt++)
#pragma unroll
            for (int nt = 0; nt < 4; nt++)
#pragma unroll
                for (int ee = 0; ee < 4; ee++) acc[mt][nt][ee] = 0.f;

#pragma unroll
        for (int ks = 0; ks < 8; ks++) {
            const int ku = ks * 2 + khalf;       // 16B unit index in k
            uint32_t a[2][4];
#pragma unroll
            for (int mt = 0; mt < 2; mt++)
                ldmx4(a[mt], sbase + swoff(wm + mt * 16 + lrow, ku));
#pragma unroll
            for (int np = 0; np < 2; np++) {
                uint32_t b[4];
                ldmx4(b, bbase + swoff(wn + np * 16 + lrow, ku));
#pragma unroll
                for (int mt = 0; mt < 2; mt++) {
                    mma16816h(acc[mt][2*np+0], a[mt], b[0], b[2]);
                    mma16816h(acc[mt][2*np+1], a[mt], b[1], b[3]);
                }
            }
        }

        // epilogue — streaming stores (overlaps with next-B prefetch)
        const int r0 = (bm << 7) + wm + r_in;
        const int c0 = (bn << 7) + wn + c_in;
#pragma unroll
        for (int mt = 0; mt < 2; mt++) {
#pragma unroll
            for (int nt = 0; nt < 4; nt++) {
                float* p0 = C + (size_t)(r0 + mt * 16)     * NR + c0 + nt * 8;
                float* p1 = C + (size_t)(r0 + mt * 16 + 8) * NR + c0 + nt * 8;
                stcs2(p0, acc[mt][nt][0], acc[mt][nt][1]);
                stcs2(p1, acc[mt][nt][2], acc[mt][nt][3]);
            }
        }
    }
}

// ===========================================================================
extern "C" void kernel_launch(void* const* d_in, const int* in_sizes, int n_in,
                              void* d_out, int out_size)
{
    const float* x  = (const float*)d_in[0];
    const float* y  = (const float*)d_in[1];
    const float* W1 = (const float*)d_in[2];
    const float* b1 = (const float*)d_in[3];
    const float* W2 = (const float*)d_in[4];
    const float* b2 = (const float*)d_in[5];
    const float* W3 = (const float*)d_in[6];
    const float* b3 = (const float*)d_in[7];
    float* out = (float*)d_out;

    __half *H1, *H2, *Zf, *WT1, *WT2, *WT3;
    cudaGetSymbolAddress((void**)&H1,  g_H1);
    cudaGetSymbolAddress((void**)&H2,  g_H2);
    cudaGetSymbolAddress((void**)&Zf,  g_Zf);
    cudaGetSymbolAddress((void**)&WT1, g_WT1);
    cudaGetSymbolAddress((void**)&WT2, g_WT2);
    cudaGetSymbolAddress((void**)&WT3, g_WT3);

    cudaFuncSetAttribute(gemm_nt_persist, cudaFuncAttributeMaxDynamicSharedMemorySize, PT_SMEM);
    cudaFuncSetAttribute(gemm_norm64, cudaFuncAttributeMaxDynamicSharedMemorySize, N3_SMEM);
    cudaFuncSetAttribute(gemm_enc<64,  true>,  cudaFuncAttributeMaxDynamicSharedMemorySize, ENC_SMEM);
    cudaFuncSetAttribute(gemm_enc<512, false>, cudaFuncAttributeMaxDynamicSharedMemorySize, ENC_SMEM);

    // launch 1, 2: weight prep
    prep_w13<<<(HID * DIM + LAT * HID + 255) / 256, 256>>>(W1, W3, WT1, WT3);
    prep_w2 <<<(HID * HID + 255) / 256, 256>>>(W2, WT2);

    // launch 3: layer 1 (fp32 x/y fused)
    dim3 g1(HID / 128, 2 * NR / 128);
    gemm_enc<64, true><<<g1, 512, ENC_SMEM>>>(x, y, WT1, b1, H1, HID);

    // launch 4 (profiled): layer 2
    dim3 g2(HID / 128, 2 * NR / 128);
    gemm_enc<512, false><<<g2, 512, ENC_SMEM>>>(H1, nullptr, WT2, b2, H2, HID);

    // launch 5: layer 3 + L2 norm (3 CTAs/SM)
    dim3 g3(1, 2 * NR / 64);
    gemm_norm64<<<g3, 256, N3_SMEM>>>(H2, WT3, b3, Zf);

    // launch 6: similarity (persistent, 296 CTAs)
    gemm_nt_persist<<<PT_CTAS, 512, PT_SMEM>>>(Zf, Zf + (size_t)NR * LAT, out);
}